// round 3
// baseline (speedup 1.0000x reference)
#include <cuda_runtime.h>
#include <cstdint>

#define MROWS 16384
#define CDIM  512
#define DDIM  1024
#define NBLK  2

// ---------------- scratch (static device globals; no allocation) ----------------
__device__ float g_XU[MROWS * CDIM];
__device__ float g_H [MROWS * CDIM];
__device__ float g_A1[MROWS * DDIM];
__device__ float g_A2[MROWS * DDIM];
__device__ float g_Xn[MROWS * CDIM];
__device__ float g_Psum[64 * CDIM];
__device__ float g_Pmax[64 * CDIM];
__device__ float g_pool[2 * CDIM];     // [avg | max]
__device__ float g_hid[2 * DDIM];      // [hid_avg | hid_max]
__device__ float g_att[CDIM];
__device__ float g_hx[2 * CDIM];       // RNN h exchange, double-buffered
__device__ int   g_flag[8];            // per-CTA step flags

__device__ __forceinline__ float sigmoidf_(float x) {
    return __fdividef(1.0f, 1.0f + __expf(-x));
}

__device__ __forceinline__ int ld_acq_(const int* p) {
    int v;
    asm volatile("ld.acquire.gpu.global.b32 %0, [%1];" : "=r"(v) : "l"(p) : "memory");
    return v;
}
__device__ __forceinline__ void st_rel_(int* p, int v) {
    asm volatile("st.release.gpu.global.b32 [%0], %1;" :: "l"(p), "r"(v) : "memory");
}

// ---------------- RNN state reset (before each RNN launch; graph-replay safe) ----
__global__ void rnn_init_kernel(float* hx, int* flags)
{
    int t = threadIdx.x;
    if (t < 2 * CDIM) hx[t] = 0.0f;
    if (t < 8) flags[t] = 0;
}

// =================================================================================
// Sequential RNN: 8 plain CTAs (co-resident; grid of 8 << 148 SMs), W register-
// resident, h exchanged through a global double buffer with release/acquire flags.
// CTA r owns output columns [r*64, r*64+64). 512 threads = 16 warps:
//   warp w: wj=w&1 (32-output half), wk=w>>1 (64-wide k stripe).
// Per step: wait flags>=t -> copy h_{t-1} (global->smem) -> partial dots ->
//   smem reduce -> sigmoid -> write h_t (global) -> fence -> publish flag t+1.
// Buffering: h_t lives in hx[(t&1)*512]; step t reads hx[((t+1)&1)*512].
// =================================================================================
__global__ void __launch_bounds__(512)
rnn_kernel(const float* __restrict__ XU, const float* __restrict__ W,
           float* __restrict__ H, int M, float* hx, int* flags)
{
    __shared__ __align__(16) float hbuf[512];
    __shared__ __align__(16) float partial[8][64];

    int rank = blockIdx.x;
    int tid = threadIdx.x;
    int w = tid >> 5, l = tid & 31;
    int wj = w & 1, wk = w >> 1;
    int jl = wj * 32 + l;            // 0..63 local output
    int jg = rank * 64 + jl;         // global output column
    int kbase = wk * 64;

    float Wreg[64];
#pragma unroll
    for (int i = 0; i < 64; i++)
        Wreg[i] = W[(size_t)(kbase + i) * 512 + jg];

    for (int t = 0; t < M; t++) {
        // ---- wait until every CTA has published h_{t-1} ----
        if (tid < 8) {
            while (ld_acq_(&flags[tid]) < t) { }
        }
        __syncthreads();

        // ---- load h_{t-1} into smem; fetch this CTA's xu slice ----
        const float* src = hx + (((t + 1) & 1) << 9);
        hbuf[tid] = src[tid];
        float xu = 0.0f;
        if (tid < 64) xu = XU[(size_t)t * 512 + rank * 64 + tid];
        __syncthreads();

        // ---- partial dot: h[kbase..kbase+64) . W[k, jg] ----
        float a0 = 0.f, a1 = 0.f, a2 = 0.f, a3 = 0.f;
        const float4* h4 = reinterpret_cast<const float4*>(&hbuf[kbase]);
#pragma unroll
        for (int i = 0; i < 16; i++) {
            float4 h = h4[i];
            a0 = fmaf(h.x, Wreg[4 * i + 0], a0);
            a1 = fmaf(h.y, Wreg[4 * i + 1], a1);
            a2 = fmaf(h.z, Wreg[4 * i + 2], a2);
            a3 = fmaf(h.w, Wreg[4 * i + 3], a3);
        }
        partial[wk][jl] = (a0 + a1) + (a2 + a3);
        __syncthreads();

        // ---- reduce, activate, publish ----
        if (tid < 64) {
            float s = xu;
#pragma unroll
            for (int q = 0; q < 8; q++) s += partial[q][tid];
            float hv = sigmoidf_(s);
            H[(size_t)t * 512 + rank * 64 + tid] = hv;
            hx[((t & 1) << 9) + rank * 64 + tid] = hv;
            __threadfence();
        }
        __syncthreads();
        if (tid == 0) st_rel_(&flags[rank], t + 1);
    }
}

// =================================================================================
// fp32 SGEMM: C[M,N] (= sigmoid?)( (A (+Aadd) * ascale_k) @ B )
// 128x128 tile, BK=16, 256 threads, 8x8 per thread, register-staged double buffer.
// =================================================================================
template<bool SCALE, bool ADD>
__device__ __forceinline__ void gemm_load_tiles(
    const float* Ap0, const float* Ap1, const float* Ad0, const float* Ad1,
    const float* Bp0, const float* Bp1, const float* __restrict__ ascale,
    int k0, int ac4, int N,
    float4& a0, float4& a1, float4& b0, float4& b1)
{
    a0 = *(const float4*)(Ap0 + k0);
    a1 = *(const float4*)(Ap1 + k0);
    if (ADD) {
        float4 d0 = *(const float4*)(Ad0 + k0);
        float4 d1 = *(const float4*)(Ad1 + k0);
        a0.x += d0.x; a0.y += d0.y; a0.z += d0.z; a0.w += d0.w;
        a1.x += d1.x; a1.y += d1.y; a1.z += d1.z; a1.w += d1.w;
    }
    if (SCALE) {
        float4 s = *(const float4*)(ascale + k0 + ac4);
        a0.x *= s.x; a0.y *= s.y; a0.z *= s.z; a0.w *= s.w;
        a1.x *= s.x; a1.y *= s.y; a1.z *= s.z; a1.w *= s.w;
    }
    b0 = *(const float4*)(Bp0 + (size_t)k0 * N);
    b1 = *(const float4*)(Bp1 + (size_t)k0 * N);
}

template<bool SIG, bool SCALE, bool ADD>
__global__ __launch_bounds__(256) void gemm_kernel(
    const float* __restrict__ A, const float* __restrict__ B, float* __restrict__ C,
    int M, int N, int K,
    const float* __restrict__ ascale, const float* __restrict__ aadd)
{
    __shared__ __align__(16) float As[16][132];
    __shared__ __align__(16) float Bs[16][132];

    int tid = threadIdx.x;
    int bm = blockIdx.y * 128, bn = blockIdx.x * 128;

    int ar  = tid >> 2;          // 0..63
    int ac4 = (tid & 3) << 2;    // 0,4,8,12
    int br  = tid >> 5;          // 0..7
    int bc4 = (tid & 31) << 2;   // 0..124

    const float* Ap0 = A + (size_t)(bm + ar) * K + ac4;
    const float* Ap1 = A + (size_t)(bm + ar + 64) * K + ac4;
    const float* Ad0 = ADD ? (aadd + (size_t)(bm + ar) * K + ac4) : nullptr;
    const float* Ad1 = ADD ? (aadd + (size_t)(bm + ar + 64) * K + ac4) : nullptr;
    const float* Bp0 = B + (size_t)br * N + bn + bc4;
    const float* Bp1 = B + (size_t)(br + 8) * N + bn + bc4;

    float4 a0, a1, b0, b1;
    float acc[8][8];
#pragma unroll
    for (int i = 0; i < 8; i++)
#pragma unroll
        for (int j = 0; j < 8; j++) acc[i][j] = 0.0f;

    gemm_load_tiles<SCALE, ADD>(Ap0, Ap1, Ad0, Ad1, Bp0, Bp1, ascale, 0, ac4, N, a0, a1, b0, b1);
    // store tile 0
    As[ac4 + 0][ar] = a0.x; As[ac4 + 1][ar] = a0.y; As[ac4 + 2][ar] = a0.z; As[ac4 + 3][ar] = a0.w;
    As[ac4 + 0][ar + 64] = a1.x; As[ac4 + 1][ar + 64] = a1.y; As[ac4 + 2][ar + 64] = a1.z; As[ac4 + 3][ar + 64] = a1.w;
    *(float4*)&Bs[br][bc4] = b0;
    *(float4*)&Bs[br + 8][bc4] = b1;
    __syncthreads();

    int ty = tid >> 4, tx = tid & 15;
    int ntiles = K >> 4;

    for (int kt = 1; kt <= ntiles; kt++) {
        if (kt < ntiles)
            gemm_load_tiles<SCALE, ADD>(Ap0, Ap1, Ad0, Ad1, Bp0, Bp1, ascale, kt * 16, ac4, N, a0, a1, b0, b1);
#pragma unroll
        for (int kk = 0; kk < 16; kk++) {
            float4 af0 = *(const float4*)&As[kk][ty * 8];
            float4 af1 = *(const float4*)&As[kk][ty * 8 + 4];
            float4 bf0 = *(const float4*)&Bs[kk][tx * 8];
            float4 bf1 = *(const float4*)&Bs[kk][tx * 8 + 4];
            float av[8] = {af0.x, af0.y, af0.z, af0.w, af1.x, af1.y, af1.z, af1.w};
            float bv[8] = {bf0.x, bf0.y, bf0.z, bf0.w, bf1.x, bf1.y, bf1.z, bf1.w};
#pragma unroll
            for (int i = 0; i < 8; i++)
#pragma unroll
                for (int j = 0; j < 8; j++)
                    acc[i][j] = fmaf(av[i], bv[j], acc[i][j]);
        }
        __syncthreads();
        if (kt < ntiles) {
            As[ac4 + 0][ar] = a0.x; As[ac4 + 1][ar] = a0.y; As[ac4 + 2][ar] = a0.z; As[ac4 + 3][ar] = a0.w;
            As[ac4 + 0][ar + 64] = a1.x; As[ac4 + 1][ar + 64] = a1.y; As[ac4 + 2][ar + 64] = a1.z; As[ac4 + 3][ar + 64] = a1.w;
            *(float4*)&Bs[br][bc4] = b0;
            *(float4*)&Bs[br + 8][bc4] = b1;
            __syncthreads();
        }
    }

#pragma unroll
    for (int i = 0; i < 8; i++) {
        int row = bm + ty * 8 + i;
        float4 o0, o1;
        if (SIG) {
            o0 = make_float4(sigmoidf_(acc[i][0]), sigmoidf_(acc[i][1]), sigmoidf_(acc[i][2]), sigmoidf_(acc[i][3]));
            o1 = make_float4(sigmoidf_(acc[i][4]), sigmoidf_(acc[i][5]), sigmoidf_(acc[i][6]), sigmoidf_(acc[i][7]));
        } else {
            o0 = make_float4(acc[i][0], acc[i][1], acc[i][2], acc[i][3]);
            o1 = make_float4(acc[i][4], acc[i][5], acc[i][6], acc[i][7]);
        }
        *(float4*)(C + (size_t)row * N + bn + tx * 8)     = o0;
        *(float4*)(C + (size_t)row * N + bn + tx * 8 + 4) = o1;
    }
}

// ---------------- pooling (deterministic 2-pass) ----------------
__global__ __launch_bounds__(256) void pool_partial_kernel(
    const float* __restrict__ Y, float* __restrict__ Psum, float* __restrict__ Pmax)
{
    int b = blockIdx.x, t = threadIdx.x;           // 64 blocks x 256 threads
    float s0 = 0.f, s1 = 0.f, m0 = -1e30f, m1 = -1e30f;
    int base = b * 256;
    for (int r = 0; r < 256; r++) {
        const float* row = Y + (size_t)(base + r) * CDIM;
        float v0 = row[t], v1 = row[t + 256];
        s0 += v0; s1 += v1;
        m0 = fmaxf(m0, v0); m1 = fmaxf(m1, v1);
    }
    Psum[b * CDIM + t] = s0;       Psum[b * CDIM + t + 256] = s1;
    Pmax[b * CDIM + t] = m0;       Pmax[b * CDIM + t + 256] = m1;
}

__global__ __launch_bounds__(512) void pool_final_kernel(
    const float* __restrict__ Psum, const float* __restrict__ Pmax, float* __restrict__ pool)
{
    int t = threadIdx.x;   // 512
    float s = 0.f, m = -1e30f;
    for (int b = 0; b < 64; b++) {
        s += Psum[b * CDIM + t];
        m = fmaxf(m, Pmax[b * CDIM + t]);
    }
    pool[t] = s * (1.0f / (float)MROWS);
    pool[CDIM + t] = m;
}

// ---------------- channel-attention MLP ----------------
__global__ __launch_bounds__(128) void att_hidden_kernel(
    const float* __restrict__ pool, const float* __restrict__ Wa1j, float* __restrict__ hid)
{
    __shared__ float p[2 * CDIM];
    int tid = threadIdx.x;
    for (int q = tid; q < 2 * CDIM; q += 128) p[q] = pool[q];
    __syncthreads();
    int i = blockIdx.x * 128 + tid;   // 0..1023
    float sa = 0.f, sm = 0.f;
    for (int k = 0; k < CDIM; k++) {
        float w = Wa1j[(size_t)k * DDIM + i];
        sa = fmaf(p[k], w, sa);
        sm = fmaf(p[CDIM + k], w, sm);
    }
    hid[i]        = fmaxf(sa, 0.f);
    hid[DDIM + i] = fmaxf(sm, 0.f);
}

__global__ __launch_bounds__(128) void att_out_kernel(
    const float* __restrict__ hid, const float* __restrict__ Wa2j,
    float* __restrict__ att, float* __restrict__ att_out)
{
    __shared__ float hsum[DDIM];
    int tid = threadIdx.x;
    for (int q = tid; q < DDIM; q += 128) hsum[q] = hid[q] + hid[DDIM + q];
    __syncthreads();
    int c = blockIdx.x * 128 + tid;   // 0..511
    float s = 0.f;
    for (int i = 0; i < DDIM; i++)
        s = fmaf(hsum[i], Wa2j[(size_t)i * CDIM + c], s);
    float a = sigmoidf_(s);
    att[c] = a;
    att_out[c] = a;
}

// ---------------- final GEMV (O = 1) ----------------
__global__ __launch_bounds__(256) void gemv_kernel(
    const float* __restrict__ X, const float* __restrict__ Wd, float* __restrict__ y)
{
    __shared__ float w[CDIM];
    int tid = threadIdx.x;
    w[tid] = Wd[tid]; w[tid + 256] = Wd[tid + 256];
    __syncthreads();
    int warp = tid >> 5, lane = tid & 31;
    int row = blockIdx.x * 8 + warp;
    const float* x = X + (size_t)row * CDIM;
    float s = 0.f;
#pragma unroll
    for (int i = 0; i < 16; i++)
        s = fmaf(x[lane + 32 * i], w[lane + 32 * i], s);
#pragma unroll
    for (int o = 16; o; o >>= 1) s += __shfl_down_sync(0xffffffffu, s, o);
    if (lane == 0) y[row] = s;
}

// ---------------- host orchestration ----------------
static void launch_gemm(const float* A, const float* B, float* C,
                        int M, int N, int K, bool sig,
                        const float* ascale, const float* aadd)
{
    dim3 g(N / 128, M / 128), b(256);
    if (sig) {
        if (ascale) gemm_kernel<true, true, false><<<g, b>>>(A, B, C, M, N, K, ascale, nullptr);
        else        gemm_kernel<true, false, false><<<g, b>>>(A, B, C, M, N, K, nullptr, nullptr);
    } else {
        if (aadd)   gemm_kernel<false, false, true><<<g, b>>>(A, B, C, M, N, K, nullptr, aadd);
        else        gemm_kernel<false, false, false><<<g, b>>>(A, B, C, M, N, K, nullptr, nullptr);
    }
}

extern "C" void kernel_launch(void* const* d_in, const int* in_sizes, int n_in,
                              void* d_out, int out_size)
{
    const float* X   = (const float*)d_in[0];
    const float* U   = (const float*)d_in[1];
    const float* W   = (const float*)d_in[2];
    const float* V   = (const float*)d_in[3];
    const float* Wd1 = (const float*)d_in[4];
    const float* Wd2 = (const float*)d_in[5];
    const float* Wd3 = (const float*)d_in[6];
    const float* Wd  = (const float*)d_in[7];
    const float* Wa1 = (const float*)d_in[8];
    const float* Wa2 = (const float*)d_in[9];

    float* out      = (float*)d_out;
    float* out_y    = out;                       // [16384]
    float* out_att  = out + MROWS;               // [2,1,512]
    float* out_data = out_att + NBLK * CDIM;     // [2,16384,512]

    float *xu, *h, *a1, *a2, *xn, *ps, *pm, *pool, *hid, *att, *hx;
    int* flags;
    cudaGetSymbolAddress((void**)&xu,    g_XU);
    cudaGetSymbolAddress((void**)&h,     g_H);
    cudaGetSymbolAddress((void**)&a1,    g_A1);
    cudaGetSymbolAddress((void**)&a2,    g_A2);
    cudaGetSymbolAddress((void**)&xn,    g_Xn);
    cudaGetSymbolAddress((void**)&ps,    g_Psum);
    cudaGetSymbolAddress((void**)&pm,    g_Pmax);
    cudaGetSymbolAddress((void**)&pool,  g_pool);
    cudaGetSymbolAddress((void**)&hid,   g_hid);
    cudaGetSymbolAddress((void**)&att,   g_att);
    cudaGetSymbolAddress((void**)&hx,    g_hx);
    cudaGetSymbolAddress((void**)&flags, g_flag);

    for (int j = 0; j < NBLK; j++) {
        const float* Ain  = (j == 0) ? X : xn;
        const float* Aadd = (j == 0) ? nullptr : X;

        // XU = (Ain [+ X]) @ U     (no activation)
        launch_gemm(Ain, U, xu, MROWS, CDIM, CDIM, false, nullptr, Aadd);

        // sequential RNN over M steps -> H (reset exchange state first)
        rnn_init_kernel<<<1, 1024>>>(hx, flags);
        rnn_kernel<<<8, 512>>>(xu, W, h, MROWS, hx, flags);

        // Y = sigmoid(H @ V) written straight into the output "data" slab
        float* Yj = out_data + (size_t)j * MROWS * CDIM;
        launch_gemm(h, V, Yj, MROWS, CDIM, CDIM, true, nullptr, nullptr);

        // channel attention
        pool_partial_kernel<<<64, 256>>>(Yj, ps, pm);
        pool_final_kernel<<<1, 512>>>(ps, pm, pool);
        att_hidden_kernel<<<8, 128>>>(pool, Wa1 + (size_t)j * CDIM * DDIM, hid);
        att_out_kernel<<<4, 128>>>(hid, Wa2 + (size_t)j * DDIM * CDIM, att,
                                   out_att + (size_t)j * CDIM);

        // dense stack with att folded into A-loads of the first GEMM
        launch_gemm(Yj, Wd1, a1, MROWS, DDIM, CDIM, true, att, nullptr);
        launch_gemm(a1, Wd2, a2, MROWS, DDIM, DDIM, true, nullptr, nullptr);
        launch_gemm(a2, Wd3, xn, MROWS, CDIM, DDIM, true, nullptr, nullptr);
    }

    // y_hat = Xn @ Wd  (O=1)
    gemv_kernel<<<MROWS / 8, 256>>>(xn, Wd, out_y);
}

// round 4
// speedup vs baseline: 1.2384x; 1.2384x over previous
#include <cuda_runtime.h>
#include <cstdint>

#define MROWS 16384
#define CDIM  512
#define DDIM  1024
#define NBLK  2

// ---------------- scratch (static device globals; no allocation) ----------------
__device__ float g_XU[MROWS * CDIM];
__device__ float g_H [MROWS * CDIM];
__device__ float g_A1[MROWS * DDIM];
__device__ float g_A2[MROWS * DDIM];
__device__ float g_Xn[MROWS * CDIM];
__device__ float g_Psum[64 * CDIM];
__device__ float g_Pmax[64 * CDIM];
__device__ float g_pool[2 * CDIM];     // [avg | max]
__device__ float g_hid[2 * DDIM];      // [hid_avg | hid_max]
__device__ float g_att[CDIM];
__device__ unsigned long long g_hpk[2 * CDIM];   // packed {tag,value} h exchange, double-buffered

__device__ __forceinline__ float sigmoidf_(float x) {
    return __fdividef(1.0f, 1.0f + __expf(-x));
}

__device__ __forceinline__ unsigned long long ld_acq64_(const unsigned long long* p) {
    unsigned long long v;
    asm volatile("ld.acquire.gpu.global.b64 %0, [%1];" : "=l"(v) : "l"(p) : "memory");
    return v;
}
__device__ __forceinline__ void st_rel64_(unsigned long long* p, unsigned long long v) {
    asm volatile("st.release.gpu.global.b64 [%0], %1;" :: "l"(p), "l"(v) : "memory");
}

// ---------------- RNN state reset (before each RNN launch; graph-replay safe) ----
__global__ void rnn_init_kernel(unsigned long long* hpk)
{
    int t = threadIdx.x;                 // 1024 threads
    hpk[t] = 0ULL;                       // value = 0.0f, tag = 0
}

// =================================================================================
// Sequential RNN: 8 plain CTAs (co-resident), W register-resident.
// h exchanged as packed 64-bit words {tag:32 | value:32} in a global double buffer.
//   - publish h_t[i]: st.release.gpu.b64  {t+1, bits(h)}  into buf[t&1]
//   - consume h_{t-1}: poll ld.acquire.gpu.b64 on buf[(t+1)&1] until tag >= t
// Single atomic word carries both readiness and data: no threadfence, no separate
// flag round trip. WAR safety: each CTA's publish is ordered after ALL its reads
// (two __syncthreads between), so tag==t anywhere implies that CTA finished its
// step t-1 reads; inductively no buffer is overwritten while still being read.
// CTA r owns output columns [r*64, r*64+64). 512 threads = 16 warps:
//   warp w: wj=w&1 (32-output half), wk=w>>1 (64-wide k stripe);
//   each thread holds a 64-deep W column stripe in registers.
// =================================================================================
__global__ void __launch_bounds__(512)
rnn_kernel(const float* __restrict__ XU, const float* __restrict__ W,
           float* __restrict__ H, int M, unsigned long long* hpk)
{
    __shared__ __align__(16) float hbuf[512];
    __shared__ __align__(16) float partial[8][64];

    int rank = blockIdx.x;
    int tid = threadIdx.x;
    int w = tid >> 5, l = tid & 31;
    int wj = w & 1, wk = w >> 1;
    int jl = wj * 32 + l;            // 0..63 local output
    int jg = rank * 64 + jl;         // global output column
    int kbase = wk * 64;

    float Wreg[64];
#pragma unroll
    for (int i = 0; i < 64; i++)
        Wreg[i] = W[(size_t)(kbase + i) * 512 + jg];

    for (int t = 0; t < M; t++) {
        // ---- poll + stage h_{t-1}: one packed word per thread ----
        const unsigned long long* src = hpk + (((t + 1) & 1) << 9);
        unsigned long long pk = ld_acq64_(&src[tid]);
        while ((int)(pk >> 32) < t) pk = ld_acq64_(&src[tid]);
        hbuf[tid] = __uint_as_float((unsigned)(pk & 0xffffffffu));

        float xu = 0.0f;
        if (tid < 64) xu = XU[(size_t)t * 512 + rank * 64 + tid];
        __syncthreads();

        // ---- partial dot: h[kbase..kbase+64) . W[k, jg] ----
        float a0 = 0.f, a1 = 0.f, a2 = 0.f, a3 = 0.f;
        const float4* h4 = reinterpret_cast<const float4*>(&hbuf[kbase]);
#pragma unroll
        for (int i = 0; i < 16; i++) {
            float4 h = h4[i];
            a0 = fmaf(h.x, Wreg[4 * i + 0], a0);
            a1 = fmaf(h.y, Wreg[4 * i + 1], a1);
            a2 = fmaf(h.z, Wreg[4 * i + 2], a2);
            a3 = fmaf(h.w, Wreg[4 * i + 3], a3);
        }
        partial[wk][jl] = (a0 + a1) + (a2 + a3);
        __syncthreads();

        // ---- reduce, activate, publish (data+tag in one atomic 64-bit store) ----
        if (tid < 64) {
            float s = xu;
#pragma unroll
            for (int q = 0; q < 8; q++) s += partial[q][tid];
            float hv = sigmoidf_(s);
            H[(size_t)t * 512 + rank * 64 + tid] = hv;
            unsigned long long out =
                ((unsigned long long)(unsigned)(t + 1) << 32) |
                (unsigned long long)__float_as_uint(hv);
            st_rel64_(&hpk[((t & 1) << 9) + rank * 64 + tid], out);
        }
    }
}

// =================================================================================
// fp32 SGEMM: C[M,N] (= sigmoid?)( (A (+Aadd) * ascale_k) @ B )
// 128x128 tile, BK=16, 256 threads, 8x8 per thread, register-staged double buffer.
// =================================================================================
template<bool SCALE, bool ADD>
__device__ __forceinline__ void gemm_load_tiles(
    const float* Ap0, const float* Ap1, const float* Ad0, const float* Ad1,
    const float* Bp0, const float* Bp1, const float* __restrict__ ascale,
    int k0, int ac4, int N,
    float4& a0, float4& a1, float4& b0, float4& b1)
{
    a0 = *(const float4*)(Ap0 + k0);
    a1 = *(const float4*)(Ap1 + k0);
    if (ADD) {
        float4 d0 = *(const float4*)(Ad0 + k0);
        float4 d1 = *(const float4*)(Ad1 + k0);
        a0.x += d0.x; a0.y += d0.y; a0.z += d0.z; a0.w += d0.w;
        a1.x += d1.x; a1.y += d1.y; a1.z += d1.z; a1.w += d1.w;
    }
    if (SCALE) {
        float4 s = *(const float4*)(ascale + k0 + ac4);
        a0.x *= s.x; a0.y *= s.y; a0.z *= s.z; a0.w *= s.w;
        a1.x *= s.x; a1.y *= s.y; a1.z *= s.z; a1.w *= s.w;
    }
    b0 = *(const float4*)(Bp0 + (size_t)k0 * N);
    b1 = *(const float4*)(Bp1 + (size_t)k0 * N);
}

template<bool SIG, bool SCALE, bool ADD>
__global__ __launch_bounds__(256) void gemm_kernel(
    const float* __restrict__ A, const float* __restrict__ B, float* __restrict__ C,
    int M, int N, int K,
    const float* __restrict__ ascale, const float* __restrict__ aadd)
{
    __shared__ __align__(16) float As[16][132];
    __shared__ __align__(16) float Bs[16][132];

    int tid = threadIdx.x;
    int bm = blockIdx.y * 128, bn = blockIdx.x * 128;

    int ar  = tid >> 2;          // 0..63
    int ac4 = (tid & 3) << 2;    // 0,4,8,12
    int br  = tid >> 5;          // 0..7
    int bc4 = (tid & 31) << 2;   // 0..124

    const float* Ap0 = A + (size_t)(bm + ar) * K + ac4;
    const float* Ap1 = A + (size_t)(bm + ar + 64) * K + ac4;
    const float* Ad0 = ADD ? (aadd + (size_t)(bm + ar) * K + ac4) : nullptr;
    const float* Ad1 = ADD ? (aadd + (size_t)(bm + ar + 64) * K + ac4) : nullptr;
    const float* Bp0 = B + (size_t)br * N + bn + bc4;
    const float* Bp1 = B + (size_t)(br + 8) * N + bn + bc4;

    float4 a0, a1, b0, b1;
    float acc[8][8];
#pragma unroll
    for (int i = 0; i < 8; i++)
#pragma unroll
        for (int j = 0; j < 8; j++) acc[i][j] = 0.0f;

    gemm_load_tiles<SCALE, ADD>(Ap0, Ap1, Ad0, Ad1, Bp0, Bp1, ascale, 0, ac4, N, a0, a1, b0, b1);
    // store tile 0
    As[ac4 + 0][ar] = a0.x; As[ac4 + 1][ar] = a0.y; As[ac4 + 2][ar] = a0.z; As[ac4 + 3][ar] = a0.w;
    As[ac4 + 0][ar + 64] = a1.x; As[ac4 + 1][ar + 64] = a1.y; As[ac4 + 2][ar + 64] = a1.z; As[ac4 + 3][ar + 64] = a1.w;
    *(float4*)&Bs[br][bc4] = b0;
    *(float4*)&Bs[br + 8][bc4] = b1;
    __syncthreads();

    int ty = tid >> 4, tx = tid & 15;
    int ntiles = K >> 4;

    for (int kt = 1; kt <= ntiles; kt++) {
        if (kt < ntiles)
            gemm_load_tiles<SCALE, ADD>(Ap0, Ap1, Ad0, Ad1, Bp0, Bp1, ascale, kt * 16, ac4, N, a0, a1, b0, b1);
#pragma unroll
        for (int kk = 0; kk < 16; kk++) {
            float4 af0 = *(const float4*)&As[kk][ty * 8];
            float4 af1 = *(const float4*)&As[kk][ty * 8 + 4];
            float4 bf0 = *(const float4*)&Bs[kk][tx * 8];
            float4 bf1 = *(const float4*)&Bs[kk][tx * 8 + 4];
            float av[8] = {af0.x, af0.y, af0.z, af0.w, af1.x, af1.y, af1.z, af1.w};
            float bv[8] = {bf0.x, bf0.y, bf0.z, bf0.w, bf1.x, bf1.y, bf1.z, bf1.w};
#pragma unroll
            for (int i = 0; i < 8; i++)
#pragma unroll
                for (int j = 0; j < 8; j++)
                    acc[i][j] = fmaf(av[i], bv[j], acc[i][j]);
        }
        __syncthreads();
        if (kt < ntiles) {
            As[ac4 + 0][ar] = a0.x; As[ac4 + 1][ar] = a0.y; As[ac4 + 2][ar] = a0.z; As[ac4 + 3][ar] = a0.w;
            As[ac4 + 0][ar + 64] = a1.x; As[ac4 + 1][ar + 64] = a1.y; As[ac4 + 2][ar + 64] = a1.z; As[ac4 + 3][ar + 64] = a1.w;
            *(float4*)&Bs[br][bc4] = b0;
            *(float4*)&Bs[br + 8][bc4] = b1;
            __syncthreads();
        }
    }

#pragma unroll
    for (int i = 0; i < 8; i++) {
        int row = bm + ty * 8 + i;
        float4 o0, o1;
        if (SIG) {
            o0 = make_float4(sigmoidf_(acc[i][0]), sigmoidf_(acc[i][1]), sigmoidf_(acc[i][2]), sigmoidf_(acc[i][3]));
            o1 = make_float4(sigmoidf_(acc[i][4]), sigmoidf_(acc[i][5]), sigmoidf_(acc[i][6]), sigmoidf_(acc[i][7]));
        } else {
            o0 = make_float4(acc[i][0], acc[i][1], acc[i][2], acc[i][3]);
            o1 = make_float4(acc[i][4], acc[i][5], acc[i][6], acc[i][7]);
        }
        *(float4*)(C + (size_t)row * N + bn + tx * 8)     = o0;
        *(float4*)(C + (size_t)row * N + bn + tx * 8 + 4) = o1;
    }
}

// ---------------- pooling (deterministic 2-pass) ----------------
__global__ __launch_bounds__(256) void pool_partial_kernel(
    const float* __restrict__ Y, float* __restrict__ Psum, float* __restrict__ Pmax)
{
    int b = blockIdx.x, t = threadIdx.x;           // 64 blocks x 256 threads
    float s0 = 0.f, s1 = 0.f, m0 = -1e30f, m1 = -1e30f;
    int base = b * 256;
    for (int r = 0; r < 256; r++) {
        const float* row = Y + (size_t)(base + r) * CDIM;
        float v0 = row[t], v1 = row[t + 256];
        s0 += v0; s1 += v1;
        m0 = fmaxf(m0, v0); m1 = fmaxf(m1, v1);
    }
    Psum[b * CDIM + t] = s0;       Psum[b * CDIM + t + 256] = s1;
    Pmax[b * CDIM + t] = m0;       Pmax[b * CDIM + t + 256] = m1;
}

__global__ __launch_bounds__(512) void pool_final_kernel(
    const float* __restrict__ Psum, const float* __restrict__ Pmax, float* __restrict__ pool)
{
    int t = threadIdx.x;   // 512
    float s = 0.f, m = -1e30f;
    for (int b = 0; b < 64; b++) {
        s += Psum[b * CDIM + t];
        m = fmaxf(m, Pmax[b * CDIM + t]);
    }
    pool[t] = s * (1.0f / (float)MROWS);
    pool[CDIM + t] = m;
}

// ---------------- channel-attention MLP ----------------
__global__ __launch_bounds__(128) void att_hidden_kernel(
    const float* __restrict__ pool, const float* __restrict__ Wa1j, float* __restrict__ hid)
{
    __shared__ float p[2 * CDIM];
    int tid = threadIdx.x;
    for (int q = tid; q < 2 * CDIM; q += 128) p[q] = pool[q];
    __syncthreads();
    int i = blockIdx.x * 128 + tid;   // 0..1023
    float sa = 0.f, sm = 0.f;
    for (int k = 0; k < CDIM; k++) {
        float w = Wa1j[(size_t)k * DDIM + i];
        sa = fmaf(p[k], w, sa);
        sm = fmaf(p[CDIM + k], w, sm);
    }
    hid[i]        = fmaxf(sa, 0.f);
    hid[DDIM + i] = fmaxf(sm, 0.f);
}

__global__ __launch_bounds__(128) void att_out_kernel(
    const float* __restrict__ hid, const float* __restrict__ Wa2j,
    float* __restrict__ att, float* __restrict__ att_out)
{
    __shared__ float hsum[DDIM];
    int tid = threadIdx.x;
    for (int q = tid; q < DDIM; q += 128) hsum[q] = hid[q] + hid[DDIM + q];
    __syncthreads();
    int c = blockIdx.x * 128 + tid;   // 0..511
    float s = 0.f;
    for (int i = 0; i < DDIM; i++)
        s = fmaf(hsum[i], Wa2j[(size_t)i * CDIM + c], s);
    float a = sigmoidf_(s);
    att[c] = a;
    att_out[c] = a;
}

// ---------------- final GEMV (O = 1) ----------------
__global__ __launch_bounds__(256) void gemv_kernel(
    const float* __restrict__ X, const float* __restrict__ Wd, float* __restrict__ y)
{
    __shared__ float w[CDIM];
    int tid = threadIdx.x;
    w[tid] = Wd[tid]; w[tid + 256] = Wd[tid + 256];
    __syncthreads();
    int warp = tid >> 5, lane = tid & 31;
    int row = blockIdx.x * 8 + warp;
    const float* x = X + (size_t)row * CDIM;
    float s = 0.f;
#pragma unroll
    for (int i = 0; i < 16; i++)
        s = fmaf(x[lane + 32 * i], w[lane + 32 * i], s);
#pragma unroll
    for (int o = 16; o; o >>= 1) s += __shfl_down_sync(0xffffffffu, s, o);
    if (lane == 0) y[row] = s;
}

// ---------------- host orchestration ----------------
static void launch_gemm(const float* A, const float* B, float* C,
                        int M, int N, int K, bool sig,
                        const float* ascale, const float* aadd)
{
    dim3 g(N / 128, M / 128), b(256);
    if (sig) {
        if (ascale) gemm_kernel<true, true, false><<<g, b>>>(A, B, C, M, N, K, ascale, nullptr);
        else        gemm_kernel<true, false, false><<<g, b>>>(A, B, C, M, N, K, nullptr, nullptr);
    } else {
        if (aadd)   gemm_kernel<false, false, true><<<g, b>>>(A, B, C, M, N, K, nullptr, aadd);
        else        gemm_kernel<false, false, false><<<g, b>>>(A, B, C, M, N, K, nullptr, nullptr);
    }
}

extern "C" void kernel_launch(void* const* d_in, const int* in_sizes, int n_in,
                              void* d_out, int out_size)
{
    const float* X   = (const float*)d_in[0];
    const float* U   = (const float*)d_in[1];
    const float* W   = (const float*)d_in[2];
    const float* V   = (const float*)d_in[3];
    const float* Wd1 = (const float*)d_in[4];
    const float* Wd2 = (const float*)d_in[5];
    const float* Wd3 = (const float*)d_in[6];
    const float* Wd  = (const float*)d_in[7];
    const float* Wa1 = (const float*)d_in[8];
    const float* Wa2 = (const float*)d_in[9];

    float* out      = (float*)d_out;
    float* out_y    = out;                       // [16384]
    float* out_att  = out + MROWS;               // [2,1,512]
    float* out_data = out_att + NBLK * CDIM;     // [2,16384,512]

    float *xu, *h, *a1, *a2, *xn, *ps, *pm, *pool, *hid, *att;
    unsigned long long* hpk;
    cudaGetSymbolAddress((void**)&xu,    g_XU);
    cudaGetSymbolAddress((void**)&h,     g_H);
    cudaGetSymbolAddress((void**)&a1,    g_A1);
    cudaGetSymbolAddress((void**)&a2,    g_A2);
    cudaGetSymbolAddress((void**)&xn,    g_Xn);
    cudaGetSymbolAddress((void**)&ps,    g_Psum);
    cudaGetSymbolAddress((void**)&pm,    g_Pmax);
    cudaGetSymbolAddress((void**)&pool,  g_pool);
    cudaGetSymbolAddress((void**)&hid,   g_hid);
    cudaGetSymbolAddress((void**)&att,   g_att);
    cudaGetSymbolAddress((void**)&hpk,   g_hpk);

    for (int j = 0; j < NBLK; j++) {
        const float* Ain  = (j == 0) ? X : xn;
        const float* Aadd = (j == 0) ? nullptr : X;

        // XU = (Ain [+ X]) @ U     (no activation)
        launch_gemm(Ain, U, xu, MROWS, CDIM, CDIM, false, nullptr, Aadd);

        // sequential RNN over M steps -> H (reset exchange state first)
        rnn_init_kernel<<<1, 1024>>>(hpk);
        rnn_kernel<<<8, 512>>>(xu, W, h, MROWS, hpk);

        // Y = sigmoid(H @ V) written straight into the output "data" slab
        float* Yj = out_data + (size_t)j * MROWS * CDIM;
        launch_gemm(h, V, Yj, MROWS, CDIM, CDIM, true, nullptr, nullptr);

        // channel attention
        pool_partial_kernel<<<64, 256>>>(Yj, ps, pm);
        pool_final_kernel<<<1, 512>>>(ps, pm, pool);
        att_hidden_kernel<<<8, 128>>>(pool, Wa1 + (size_t)j * CDIM * DDIM, hid);
        att_out_kernel<<<4, 128>>>(hid, Wa2 + (size_t)j * DDIM * CDIM, att,
                                   out_att + (size_t)j * CDIM);

        // dense stack with att folded into A-loads of the first GEMM
        launch_gemm(Yj, Wd1, a1, MROWS, DDIM, CDIM, true, att, nullptr);
        launch_gemm(a1, Wd2, a2, MROWS, DDIM, DDIM, true, nullptr, nullptr);
        launch_gemm(a2, Wd3, xn, MROWS, CDIM, DDIM, true, nullptr, nullptr);
    }

    // y_hat = Xn @ Wd  (O=1)
    gemv_kernel<<<MROWS / 8, 256>>>(xn, Wd, out_y);
}

// round 5
// speedup vs baseline: 1.4364x; 1.1599x over previous
#include <cuda_runtime.h>
#include <cstdint>

#define MROWS 16384
#define CDIM  512
#define DDIM  1024
#define NBLK  2

#define RNN_CTAS 16          // CTAs in RNN kernel; each owns 512/16 = 32 columns
#define RCOLS    32          // columns per CTA == stripe width

// ---------------- scratch (static device globals; no allocation) ----------------
__device__ float g_XU[MROWS * CDIM];
__device__ float g_H [MROWS * CDIM];
__device__ float g_A1[MROWS * DDIM];
__device__ float g_A2[MROWS * DDIM];
__device__ float g_Xn[MROWS * CDIM];
__device__ float g_Psum[64 * CDIM];
__device__ float g_Pmax[64 * CDIM];
__device__ float g_pool[2 * CDIM];     // [avg | max]
__device__ float g_hid[2 * DDIM];      // [hid_avg | hid_max]
__device__ float g_att[CDIM];
__device__ unsigned long long g_hpk[2 * CDIM];   // packed {tag,value} h exchange, double-buffered

__device__ __forceinline__ float sigmoidf_(float x) {
    return __fdividef(1.0f, 1.0f + __expf(-x));
}

__device__ __forceinline__ unsigned long long ld_acq64_(const unsigned long long* p) {
    unsigned long long v;
    asm volatile("ld.acquire.gpu.global.b64 %0, [%1];" : "=l"(v) : "l"(p) : "memory");
    return v;
}
__device__ __forceinline__ void st_rel64_(unsigned long long* p, unsigned long long v) {
    asm volatile("st.release.gpu.global.b64 [%0], %1;" :: "l"(p), "l"(v) : "memory");
}

// ---------------- RNN state reset (before each RNN launch; graph-replay safe) ----
__global__ void rnn_init_kernel(unsigned long long* hpk)
{
    int t = threadIdx.x;                 // 1024 threads
    hpk[t] = 0ULL;                       // value = 0.0f, tag = 0
}

// =================================================================================
// Sequential RNN, stripe-pipelined across 16 CTAs.
//   - CTA r owns output columns [r*32, r*32+32); publishes them as packed
//     {tag:32 | value:32} words via st.release.gpu.b64 (double-buffered by t&1).
//   - Warp w of every CTA owns k-stripe w == the 32 words produced by CTA w.
//     It polls ONLY those words, stages them, and immediately computes that
//     stripe's FMA contribution: waiting for slow producers overlaps with
//     computing on stripes that already arrived.
//   - Thread (w,l): 32 FMAs, W[w*32+i][rank*32+l] register-resident (32 regs).
//   - Tail: one __syncthreads, warp 0 sums the 16 partials per column,
//     applies sigmoid, stores H, publishes, and prefetches next XU slice.
// WAR safety of the double buffers follows from tag induction: a tag t+1 from
// CTA c implies c finished all its step-t reads; partial[] is additionally
// double-buffered by step parity.
// =================================================================================
__global__ void __launch_bounds__(512)
rnn_kernel(const float* __restrict__ XU, const float* __restrict__ W,
           float* __restrict__ H, int M, unsigned long long* hpk)
{
    __shared__ __align__(16) float hs[16][RCOLS];        // staged h, stripe-major
    __shared__ float partial[2][16][RCOLS + 1];          // padded (bank spread)

    int rank = blockIdx.x;
    int tid = threadIdx.x;
    int w = tid >> 5, l = tid & 31;
    int col = (rank << 5) + l;           // this CTA's output column (warp-0 tail)

    // W stripe: thread (w,l) holds W[w*32+i][col'] where col' = rank*32 + l
    float Wreg[RCOLS];
#pragma unroll
    for (int i = 0; i < RCOLS; i++)
        Wreg[i] = W[(size_t)((w << 5) + i) * CDIM + (rank << 5) + l];

    float xu = (w == 0) ? XU[col] : 0.0f;   // step-0 slice, prefetched

    for (int t = 0; t < M; t++) {
        int cur = t & 1;

        // ---- poll + stage this warp's stripe (one packed word per thread) ----
        const unsigned long long* src = hpk + (((t + 1) & 1) << 9);
        unsigned long long pk = ld_acq64_(&src[(w << 5) + l]);
        while ((int)(pk >> 32) < t) pk = ld_acq64_(&src[(w << 5) + l]);
        hs[w][l] = __uint_as_float((unsigned)(pk & 0xffffffffu));
        __syncwarp();

        // ---- stripe FMA: 32 MACs per thread, broadcast LDS of staged h ----
        float a0 = 0.f, a1 = 0.f, a2 = 0.f, a3 = 0.f;
        const float4* h4 = reinterpret_cast<const float4*>(hs[w]);
#pragma unroll
        for (int i = 0; i < 8; i++) {
            float4 h = h4[i];
            a0 = fmaf(h.x, Wreg[4 * i + 0], a0);
            a1 = fmaf(h.y, Wreg[4 * i + 1], a1);
            a2 = fmaf(h.z, Wreg[4 * i + 2], a2);
            a3 = fmaf(h.w, Wreg[4 * i + 3], a3);
        }
        partial[cur][w][l] = (a0 + a1) + (a2 + a3);
        __syncthreads();

        // ---- tail: reduce 16 stripes, activate, publish, prefetch ----
        if (w == 0) {
            float s = xu;
#pragma unroll
            for (int q = 0; q < 16; q++) s += partial[cur][q][l];
            float hv = sigmoidf_(s);
            H[(size_t)t * CDIM + col] = hv;
            unsigned long long outw =
                ((unsigned long long)(unsigned)(t + 1) << 32) |
                (unsigned long long)__float_as_uint(hv);
            st_rel64_(&hpk[((t & 1) << 9) + col], outw);
            xu = (t + 1 < M) ? XU[(size_t)(t + 1) * CDIM + col] : 0.0f;
        }
    }
}

// =================================================================================
// fp32 SGEMM: C[M,N] (= sigmoid?)( (A (+Aadd) * ascale_k) @ B )
// 128x128 tile, BK=16, 256 threads, 8x8 per thread, register-staged double buffer.
// =================================================================================
template<bool SCALE, bool ADD>
__device__ __forceinline__ void gemm_load_tiles(
    const float* Ap0, const float* Ap1, const float* Ad0, const float* Ad1,
    const float* Bp0, const float* Bp1, const float* __restrict__ ascale,
    int k0, int ac4, int N,
    float4& a0, float4& a1, float4& b0, float4& b1)
{
    a0 = *(const float4*)(Ap0 + k0);
    a1 = *(const float4*)(Ap1 + k0);
    if (ADD) {
        float4 d0 = *(const float4*)(Ad0 + k0);
        float4 d1 = *(const float4*)(Ad1 + k0);
        a0.x += d0.x; a0.y += d0.y; a0.z += d0.z; a0.w += d0.w;
        a1.x += d1.x; a1.y += d1.y; a1.z += d1.z; a1.w += d1.w;
    }
    if (SCALE) {
        float4 s = *(const float4*)(ascale + k0 + ac4);
        a0.x *= s.x; a0.y *= s.y; a0.z *= s.z; a0.w *= s.w;
        a1.x *= s.x; a1.y *= s.y; a1.z *= s.z; a1.w *= s.w;
    }
    b0 = *(const float4*)(Bp0 + (size_t)k0 * N);
    b1 = *(const float4*)(Bp1 + (size_t)k0 * N);
}

template<bool SIG, bool SCALE, bool ADD>
__global__ __launch_bounds__(256) void gemm_kernel(
    const float* __restrict__ A, const float* __restrict__ B, float* __restrict__ C,
    int M, int N, int K,
    const float* __restrict__ ascale, const float* __restrict__ aadd)
{
    __shared__ __align__(16) float As[16][132];
    __shared__ __align__(16) float Bs[16][132];

    int tid = threadIdx.x;
    int bm = blockIdx.y * 128, bn = blockIdx.x * 128;

    int ar  = tid >> 2;          // 0..63
    int ac4 = (tid & 3) << 2;    // 0,4,8,12
    int br  = tid >> 5;          // 0..7
    int bc4 = (tid & 31) << 2;   // 0..124

    const float* Ap0 = A + (size_t)(bm + ar) * K + ac4;
    const float* Ap1 = A + (size_t)(bm + ar + 64) * K + ac4;
    const float* Ad0 = ADD ? (aadd + (size_t)(bm + ar) * K + ac4) : nullptr;
    const float* Ad1 = ADD ? (aadd + (size_t)(bm + ar + 64) * K + ac4) : nullptr;
    const float* Bp0 = B + (size_t)br * N + bn + bc4;
    const float* Bp1 = B + (size_t)(br + 8) * N + bn + bc4;

    float4 a0, a1, b0, b1;
    float acc[8][8];
#pragma unroll
    for (int i = 0; i < 8; i++)
#pragma unroll
        for (int j = 0; j < 8; j++) acc[i][j] = 0.0f;

    gemm_load_tiles<SCALE, ADD>(Ap0, Ap1, Ad0, Ad1, Bp0, Bp1, ascale, 0, ac4, N, a0, a1, b0, b1);
    // store tile 0
    As[ac4 + 0][ar] = a0.x; As[ac4 + 1][ar] = a0.y; As[ac4 + 2][ar] = a0.z; As[ac4 + 3][ar] = a0.w;
    As[ac4 + 0][ar + 64] = a1.x; As[ac4 + 1][ar + 64] = a1.y; As[ac4 + 2][ar + 64] = a1.z; As[ac4 + 3][ar + 64] = a1.w;
    *(float4*)&Bs[br][bc4] = b0;
    *(float4*)&Bs[br + 8][bc4] = b1;
    __syncthreads();

    int ty = tid >> 4, tx = tid & 15;
    int ntiles = K >> 4;

    for (int kt = 1; kt <= ntiles; kt++) {
        if (kt < ntiles)
            gemm_load_tiles<SCALE, ADD>(Ap0, Ap1, Ad0, Ad1, Bp0, Bp1, ascale, kt * 16, ac4, N, a0, a1, b0, b1);
#pragma unroll
        for (int kk = 0; kk < 16; kk++) {
            float4 af0 = *(const float4*)&As[kk][ty * 8];
            float4 af1 = *(const float4*)&As[kk][ty * 8 + 4];
            float4 bf0 = *(const float4*)&Bs[kk][tx * 8];
            float4 bf1 = *(const float4*)&Bs[kk][tx * 8 + 4];
            float av[8] = {af0.x, af0.y, af0.z, af0.w, af1.x, af1.y, af1.z, af1.w};
            float bv[8] = {bf0.x, bf0.y, bf0.z, bf0.w, bf1.x, bf1.y, bf1.z, bf1.w};
#pragma unroll
            for (int i = 0; i < 8; i++)
#pragma unroll
                for (int j = 0; j < 8; j++)
                    acc[i][j] = fmaf(av[i], bv[j], acc[i][j]);
        }
        __syncthreads();
        if (kt < ntiles) {
            As[ac4 + 0][ar] = a0.x; As[ac4 + 1][ar] = a0.y; As[ac4 + 2][ar] = a0.z; As[ac4 + 3][ar] = a0.w;
            As[ac4 + 0][ar + 64] = a1.x; As[ac4 + 1][ar + 64] = a1.y; As[ac4 + 2][ar + 64] = a1.z; As[ac4 + 3][ar + 64] = a1.w;
            *(float4*)&Bs[br][bc4] = b0;
            *(float4*)&Bs[br + 8][bc4] = b1;
            __syncthreads();
        }
    }

#pragma unroll
    for (int i = 0; i < 8; i++) {
        int row = bm + ty * 8 + i;
        float4 o0, o1;
        if (SIG) {
            o0 = make_float4(sigmoidf_(acc[i][0]), sigmoidf_(acc[i][1]), sigmoidf_(acc[i][2]), sigmoidf_(acc[i][3]));
            o1 = make_float4(sigmoidf_(acc[i][4]), sigmoidf_(acc[i][5]), sigmoidf_(acc[i][6]), sigmoidf_(acc[i][7]));
        } else {
            o0 = make_float4(acc[i][0], acc[i][1], acc[i][2], acc[i][3]);
            o1 = make_float4(acc[i][4], acc[i][5], acc[i][6], acc[i][7]);
        }
        *(float4*)(C + (size_t)row * N + bn + tx * 8)     = o0;
        *(float4*)(C + (size_t)row * N + bn + tx * 8 + 4) = o1;
    }
}

// ---------------- pooling (deterministic 2-pass) ----------------
__global__ __launch_bounds__(256) void pool_partial_kernel(
    const float* __restrict__ Y, float* __restrict__ Psum, float* __restrict__ Pmax)
{
    int b = blockIdx.x, t = threadIdx.x;           // 64 blocks x 256 threads
    float s0 = 0.f, s1 = 0.f, m0 = -1e30f, m1 = -1e30f;
    int base = b * 256;
    for (int r = 0; r < 256; r++) {
        const float* row = Y + (size_t)(base + r) * CDIM;
        float v0 = row[t], v1 = row[t + 256];
        s0 += v0; s1 += v1;
        m0 = fmaxf(m0, v0); m1 = fmaxf(m1, v1);
    }
    Psum[b * CDIM + t] = s0;       Psum[b * CDIM + t + 256] = s1;
    Pmax[b * CDIM + t] = m0;       Pmax[b * CDIM + t + 256] = m1;
}

__global__ __launch_bounds__(512) void pool_final_kernel(
    const float* __restrict__ Psum, const float* __restrict__ Pmax, float* __restrict__ pool)
{
    int t = threadIdx.x;   // 512
    float s = 0.f, m = -1e30f;
    for (int b = 0; b < 64; b++) {
        s += Psum[b * CDIM + t];
        m = fmaxf(m, Pmax[b * CDIM + t]);
    }
    pool[t] = s * (1.0f / (float)MROWS);
    pool[CDIM + t] = m;
}

// ---------------- channel-attention MLP ----------------
__global__ __launch_bounds__(128) void att_hidden_kernel(
    const float* __restrict__ pool, const float* __restrict__ Wa1j, float* __restrict__ hid)
{
    __shared__ float p[2 * CDIM];
    int tid = threadIdx.x;
    for (int q = tid; q < 2 * CDIM; q += 128) p[q] = pool[q];
    __syncthreads();
    int i = blockIdx.x * 128 + tid;   // 0..1023
    float sa = 0.f, sm = 0.f;
    for (int k = 0; k < CDIM; k++) {
        float w = Wa1j[(size_t)k * DDIM + i];
        sa = fmaf(p[k], w, sa);
        sm = fmaf(p[CDIM + k], w, sm);
    }
    hid[i]        = fmaxf(sa, 0.f);
    hid[DDIM + i] = fmaxf(sm, 0.f);
}

__global__ __launch_bounds__(128) void att_out_kernel(
    const float* __restrict__ hid, const float* __restrict__ Wa2j,
    float* __restrict__ att, float* __restrict__ att_out)
{
    __shared__ float hsum[DDIM];
    int tid = threadIdx.x;
    for (int q = tid; q < DDIM; q += 128) hsum[q] = hid[q] + hid[DDIM + q];
    __syncthreads();
    int c = blockIdx.x * 128 + tid;   // 0..511
    float s = 0.f;
    for (int i = 0; i < DDIM; i++)
        s = fmaf(hsum[i], Wa2j[(size_t)i * CDIM + c], s);
    float a = sigmoidf_(s);
    att[c] = a;
    att_out[c] = a;
}

// ---------------- final GEMV (O = 1) ----------------
__global__ __launch_bounds__(256) void gemv_kernel(
    const float* __restrict__ X, const float* __restrict__ Wd, float* __restrict__ y)
{
    __shared__ float w[CDIM];
    int tid = threadIdx.x;
    w[tid] = Wd[tid]; w[tid + 256] = Wd[tid + 256];
    __syncthreads();
    int warp = tid >> 5, lane = tid & 31;
    int row = blockIdx.x * 8 + warp;
    const float* x = X + (size_t)row * CDIM;
    float s = 0.f;
#pragma unroll
    for (int i = 0; i < 16; i++)
        s = fmaf(x[lane + 32 * i], w[lane + 32 * i], s);
#pragma unroll
    for (int o = 16; o; o >>= 1) s += __shfl_down_sync(0xffffffffu, s, o);
    if (lane == 0) y[row] = s;
}

// ---------------- host orchestration ----------------
static void launch_gemm(const float* A, const float* B, float* C,
                        int M, int N, int K, bool sig,
                        const float* ascale, const float* aadd)
{
    dim3 g(N / 128, M / 128), b(256);
    if (sig) {
        if (ascale) gemm_kernel<true, true, false><<<g, b>>>(A, B, C, M, N, K, ascale, nullptr);
        else        gemm_kernel<true, false, false><<<g, b>>>(A, B, C, M, N, K, nullptr, nullptr);
    } else {
        if (aadd)   gemm_kernel<false, false, true><<<g, b>>>(A, B, C, M, N, K, nullptr, aadd);
        else        gemm_kernel<false, false, false><<<g, b>>>(A, B, C, M, N, K, nullptr, nullptr);
    }
}

extern "C" void kernel_launch(void* const* d_in, const int* in_sizes, int n_in,
                              void* d_out, int out_size)
{
    const float* X   = (const float*)d_in[0];
    const float* U   = (const float*)d_in[1];
    const float* W   = (const float*)d_in[2];
    const float* V   = (const float*)d_in[3];
    const float* Wd1 = (const float*)d_in[4];
    const float* Wd2 = (const float*)d_in[5];
    const float* Wd3 = (const float*)d_in[6];
    const float* Wd  = (const float*)d_in[7];
    const float* Wa1 = (const float*)d_in[8];
    const float* Wa2 = (const float*)d_in[9];

    float* out      = (float*)d_out;
    float* out_y    = out;                       // [16384]
    float* out_att  = out + MROWS;               // [2,1,512]
    float* out_data = out_att + NBLK * CDIM;     // [2,16384,512]

    float *xu, *h, *a1, *a2, *xn, *ps, *pm, *pool, *hid, *att;
    unsigned long long* hpk;
    cudaGetSymbolAddress((void**)&xu,    g_XU);
    cudaGetSymbolAddress((void**)&h,     g_H);
    cudaGetSymbolAddress((void**)&a1,    g_A1);
    cudaGetSymbolAddress((void**)&a2,    g_A2);
    cudaGetSymbolAddress((void**)&xn,    g_Xn);
    cudaGetSymbolAddress((void**)&ps,    g_Psum);
    cudaGetSymbolAddress((void**)&pm,    g_Pmax);
    cudaGetSymbolAddress((void**)&pool,  g_pool);
    cudaGetSymbolAddress((void**)&hid,   g_hid);
    cudaGetSymbolAddress((void**)&att,   g_att);
    cudaGetSymbolAddress((void**)&hpk,   g_hpk);

    for (int j = 0; j < NBLK; j++) {
        const float* Ain  = (j == 0) ? X : xn;
        const float* Aadd = (j == 0) ? nullptr : X;

        // XU = (Ain [+ X]) @ U     (no activation)
        launch_gemm(Ain, U, xu, MROWS, CDIM, CDIM, false, nullptr, Aadd);

        // sequential RNN over M steps -> H (reset exchange state first)
        rnn_init_kernel<<<1, 1024>>>(hpk);
        rnn_kernel<<<RNN_CTAS, 512>>>(xu, W, h, MROWS, hpk);

        // Y = sigmoid(H @ V) written straight into the output "data" slab
        float* Yj = out_data + (size_t)j * MROWS * CDIM;
        launch_gemm(h, V, Yj, MROWS, CDIM, CDIM, true, nullptr, nullptr);

        // channel attention
        pool_partial_kernel<<<64, 256>>>(Yj, ps, pm);
        pool_final_kernel<<<1, 512>>>(ps, pm, pool);
        att_hidden_kernel<<<8, 128>>>(pool, Wa1 + (size_t)j * CDIM * DDIM, hid);
        att_out_kernel<<<4, 128>>>(hid, Wa2 + (size_t)j * DDIM * CDIM, att,
                                   out_att + (size_t)j * CDIM);

        // dense stack with att folded into A-loads of the first GEMM
        launch_gemm(Yj, Wd1, a1, MROWS, DDIM, CDIM, true, att, nullptr);
        launch_gemm(a1, Wd2, a2, MROWS, DDIM, DDIM, true, nullptr, nullptr);
        launch_gemm(a2, Wd3, xn, MROWS, CDIM, DDIM, true, nullptr, nullptr);
    }

    // y_hat = Xn @ Wd  (O=1)
    gemv_kernel<<<MROWS / 8, 256>>>(xn, Wd, out_y);
}

// round 9
// speedup vs baseline: 1.4895x; 1.0370x over previous
#include <cuda_runtime.h>
#include <cstdint>

#define MROWS 16384
#define CDIM  512
#define DDIM  1024
#define NBLK  2

#define RNN_CTAS 16          // CTAs in RNN kernel; each owns 512/16 = 32 columns
#define RCOLS    32          // columns per CTA == stripe width

// ---------------- scratch (static device globals; no allocation) ----------------
__device__ float g_XU[MROWS * CDIM];
__device__ float g_H [MROWS * CDIM];
__device__ float g_A1[MROWS * DDIM];
__device__ float g_A2[MROWS * DDIM];
__device__ float g_Xn[MROWS * CDIM];
__device__ float g_Psum[64 * CDIM];
__device__ float g_Pmax[64 * CDIM];
__device__ float g_pool[2 * CDIM];     // [avg | max]
__device__ float g_hid[2 * DDIM];      // [hid_avg | hid_max]
__device__ float g_att[CDIM];
__device__ unsigned long long g_hpk[2 * CDIM];   // packed {tag,value} h exchange, double-buffered

__device__ __forceinline__ float sigmoidf_(float x) {
    return __fdividef(1.0f, 1.0f + __expf(-x));
}

// Polls: ld.RELAXED.gpu — morally strong => single-copy-ATOMIC for the aligned
// 64-bit word (tag+value can't tear), but no acquire ordering cost. R7/R8 used
// weak ld.cv, which the PTX memory model does NOT guarantee atomic: tag half
// fresh + value half stale => rel_err ~5e-3. R5's ld.acquire was correct for
// the same reason (strong), just over-ordered.
// Publish: st.release.gpu — orders the producer's prior accesses behind the
// tag becoming visible (required by the tag-induction WAR proof).
__device__ __forceinline__ unsigned long long ld_rlx64_(const unsigned long long* p) {
    unsigned long long v;
    asm volatile("ld.relaxed.gpu.global.b64 %0, [%1];" : "=l"(v) : "l"(p) : "memory");
    return v;
}
__device__ __forceinline__ void st_rel64_(unsigned long long* p, unsigned long long v) {
    asm volatile("st.release.gpu.global.b64 [%0], %1;" :: "l"(p), "l"(v) : "memory");
}

// ---------------- RNN state reset (before each RNN launch; graph-replay safe) ----
__global__ void rnn_init_kernel(unsigned long long* hpk)
{
    int t = threadIdx.x;                 // 1024 threads
    hpk[t] = 0ULL;                       // value = 0.0f, tag = 0
}

// =================================================================================
// Sequential RNN, stripe-pipelined across 16 CTAs (no clusters — broker kills
// cluster launches, established R1/R2/R6).
//   - CTA r owns output columns [r*32, r*32+32); publishes packed {tag|value}
//     words via st.release.gpu.b64, parity-double-buffered by t&1.
//   - Warp w polls ONLY the 32 words of CTA w (its k-stripe) with ld.relaxed,
//     stages, and immediately runs that stripe's 32 FMAs — late producers
//     overlap with compute on stripes already arrived.
//   - XU PREFETCH RING: warp 1 keeps a 4-slot smem ring of XU rows. At iter t
//     it stores the step-t+2 value (LDG issued at iter t-1, so the STS never
//     stalls on DRAM) and issues the step-t+3 load. Warp 0's tail reads xu
//     from smem — the ~600-cycle DRAM load is off the serial path.
//     Ring safety: write@t (pre-barrier) -> read@t+2 (post-barrier) ->
//     rewrite@t+4; closed by the per-iteration __syncthreads.
//   - Tail (warp 0): reduce 16 partials, sigmoid, store H, release-publish.
// WAR safety by tag induction: tag t+1 from CTA c implies c's step-t tail ran,
// which is after c's __syncthreads, hence after ALL c's warps' step-t loads
// completed; so no parity slot is overwritten while still being read.
// =================================================================================
__global__ void __launch_bounds__(512)
rnn_kernel(const float* __restrict__ XU, const float* __restrict__ W,
           float* __restrict__ H, int M, unsigned long long* hpk)
{
    __shared__ __align__(16) float hs[16][RCOLS];        // staged h, stripe-major
    __shared__ float partial[2][16][RCOLS + 1];          // padded (bank spread)
    __shared__ float xubuf[4][RCOLS];                    // XU ring: slot s%4 = step s

    int rank = blockIdx.x;
    int tid = threadIdx.x;
    int w = tid >> 5, l = tid & 31;
    int col = (rank << 5) + l;           // this CTA's output column

    // W stripe: thread (w,l) holds W[w*32+i][rank*32+l]
    float Wreg[RCOLS];
#pragma unroll
    for (int i = 0; i < RCOLS; i++)
        Wreg[i] = W[(size_t)((w << 5) + i) * CDIM + (rank << 5) + l];

    // XU ring preload (warp 1): slots 0,1 = steps 0,1; register = step 2
    float xu_reg = 0.0f;
    if (w == 1) {
        xubuf[0][l] = XU[col];
        xubuf[1][l] = XU[(size_t)1 * CDIM + col];
        xu_reg      = XU[(size_t)2 * CDIM + col];
    }

    for (int t = 0; t < M; t++) {
        int cur = t & 1;

        // ---- poll + stage this warp's stripe (one packed word per thread) ----
        const unsigned long long* src = hpk + (((t + 1) & 1) << 9);
        unsigned long long pk = ld_rlx64_(&src[(w << 5) + l]);
        while ((int)(pk >> 32) < t) pk = ld_rlx64_(&src[(w << 5) + l]);
        hs[w][l] = __uint_as_float((unsigned)(pk & 0xffffffffu));
        __syncwarp();

        // ---- stripe FMA: 32 MACs per thread, broadcast LDS of staged h ----
        float a0 = 0.f, a1 = 0.f, a2 = 0.f, a3 = 0.f;
        const float4* h4 = reinterpret_cast<const float4*>(hs[w]);
#pragma unroll
        for (int i = 0; i < 8; i++) {
            float4 h = h4[i];
            a0 = fmaf(h.x, Wreg[4 * i + 0], a0);
            a1 = fmaf(h.y, Wreg[4 * i + 1], a1);
            a2 = fmaf(h.z, Wreg[4 * i + 2], a2);
            a3 = fmaf(h.w, Wreg[4 * i + 3], a3);
        }
        partial[cur][w][l] = (a0 + a1) + (a2 + a3);

        // ---- warp 1: service the XU ring (value arrived ~1 iter ago; no stall) ----
        if (w == 1) {
            if (t + 2 < M) xubuf[(t + 2) & 3][l] = xu_reg;
            xu_reg = (t + 3 < M) ? XU[(size_t)(t + 3) * CDIM + col] : 0.0f;
        }
        __syncthreads();

        // ---- tail: reduce 16 stripes, activate, release-publish ----
        if (w == 0) {
            float s = xubuf[t & 3][l];
#pragma unroll
            for (int q = 0; q < 16; q++) s += partial[cur][q][l];
            float hv = sigmoidf_(s);
            H[(size_t)t * CDIM + col] = hv;
            unsigned long long outw =
                ((unsigned long long)(unsigned)(t + 1) << 32) |
                (unsigned long long)__float_as_uint(hv);
            st_rel64_(&hpk[((t & 1) << 9) + col], outw);
        }
    }
}

// =================================================================================
// fp32 SGEMM: C[M,N] (= sigmoid?)( (A (+Aadd) * ascale_k) @ B )
// 128x128 tile, BK=16, 256 threads, 8x8 per thread, register-staged double buffer.
// =================================================================================
template<bool SCALE, bool ADD>
__device__ __forceinline__ void gemm_load_tiles(
    const float* Ap0, const float* Ap1, const float* Ad0, const float* Ad1,
    const float* Bp0, const float* Bp1, const float* __restrict__ ascale,
    int k0, int ac4, int N,
    float4& a0, float4& a1, float4& b0, float4& b1)
{
    a0 = *(const float4*)(Ap0 + k0);
    a1 = *(const float4*)(Ap1 + k0);
    if (ADD) {
        float4 d0 = *(const float4*)(Ad0 + k0);
        float4 d1 = *(const float4*)(Ad1 + k0);
        a0.x += d0.x; a0.y += d0.y; a0.z += d0.z; a0.w += d0.w;
        a1.x += d1.x; a1.y += d1.y; a1.z += d1.z; a1.w += d1.w;
    }
    if (SCALE) {
        float4 s = *(const float4*)(ascale + k0 + ac4);
        a0.x *= s.x; a0.y *= s.y; a0.z *= s.z; a0.w *= s.w;
        a1.x *= s.x; a1.y *= s.y; a1.z *= s.z; a1.w *= s.w;
    }
    b0 = *(const float4*)(Bp0 + (size_t)k0 * N);
    b1 = *(const float4*)(Bp1 + (size_t)k0 * N);
}

template<bool SIG, bool SCALE, bool ADD>
__global__ __launch_bounds__(256) void gemm_kernel(
    const float* __restrict__ A, const float* __restrict__ B, float* __restrict__ C,
    int M, int N, int K,
    const float* __restrict__ ascale, const float* __restrict__ aadd)
{
    __shared__ __align__(16) float As[16][132];
    __shared__ __align__(16) float Bs[16][132];

    int tid = threadIdx.x;
    int bm = blockIdx.y * 128, bn = blockIdx.x * 128;

    int ar  = tid >> 2;          // 0..63
    int ac4 = (tid & 3) << 2;    // 0,4,8,12
    int br  = tid >> 5;          // 0..7
    int bc4 = (tid & 31) << 2;   // 0..124

    const float* Ap0 = A + (size_t)(bm + ar) * K + ac4;
    const float* Ap1 = A + (size_t)(bm + ar + 64) * K + ac4;
    const float* Ad0 = ADD ? (aadd + (size_t)(bm + ar) * K + ac4) : nullptr;
    const float* Ad1 = ADD ? (aadd + (size_t)(bm + ar + 64) * K + ac4) : nullptr;
    const float* Bp0 = B + (size_t)br * N + bn + bc4;
    const float* Bp1 = B + (size_t)(br + 8) * N + bn + bc4;

    float4 a0, a1, b0, b1;
    float acc[8][8];
#pragma unroll
    for (int i = 0; i < 8; i++)
#pragma unroll
        for (int j = 0; j < 8; j++) acc[i][j] = 0.0f;

    gemm_load_tiles<SCALE, ADD>(Ap0, Ap1, Ad0, Ad1, Bp0, Bp1, ascale, 0, ac4, N, a0, a1, b0, b1);
    // store tile 0
    As[ac4 + 0][ar] = a0.x; As[ac4 + 1][ar] = a0.y; As[ac4 + 2][ar] = a0.z; As[ac4 + 3][ar] = a0.w;
    As[ac4 + 0][ar + 64] = a1.x; As[ac4 + 1][ar + 64] = a1.y; As[ac4 + 2][ar + 64] = a1.z; As[ac4 + 3][ar + 64] = a1.w;
    *(float4*)&Bs[br][bc4] = b0;
    *(float4*)&Bs[br + 8][bc4] = b1;
    __syncthreads();

    int ty = tid >> 4, tx = tid & 15;
    int ntiles = K >> 4;

    for (int kt = 1; kt <= ntiles; kt++) {
        if (kt < ntiles)
            gemm_load_tiles<SCALE, ADD>(Ap0, Ap1, Ad0, Ad1, Bp0, Bp1, ascale, kt * 16, ac4, N, a0, a1, b0, b1);
#pragma unroll
        for (int kk = 0; kk < 16; kk++) {
            float4 af0 = *(const float4*)&As[kk][ty * 8];
            float4 af1 = *(const float4*)&As[kk][ty * 8 + 4];
            float4 bf0 = *(const float4*)&Bs[kk][tx * 8];
            float4 bf1 = *(const float4*)&Bs[kk][tx * 8 + 4];
            float av[8] = {af0.x, af0.y, af0.z, af0.w, af1.x, af1.y, af1.z, af1.w};
            float bv[8] = {bf0.x, bf0.y, bf0.z, bf0.w, bf1.x, bf1.y, bf1.z, bf1.w};
#pragma unroll
            for (int i = 0; i < 8; i++)
#pragma unroll
                for (int j = 0; j < 8; j++)
                    acc[i][j] = fmaf(av[i], bv[j], acc[i][j]);
        }
        __syncthreads();
        if (kt < ntiles) {
            As[ac4 + 0][ar] = a0.x; As[ac4 + 1][ar] = a0.y; As[ac4 + 2][ar] = a0.z; As[ac4 + 3][ar] = a0.w;
            As[ac4 + 0][ar + 64] = a1.x; As[ac4 + 1][ar + 64] = a1.y; As[ac4 + 2][ar + 64] = a1.z; As[ac4 + 3][ar + 64] = a1.w;
            *(float4*)&Bs[br][bc4] = b0;
            *(float4*)&Bs[br + 8][bc4] = b1;
            __syncthreads();
        }
    }

#pragma unroll
    for (int i = 0; i < 8; i++) {
        int row = bm + ty * 8 + i;
        float4 o0, o1;
        if (SIG) {
            o0 = make_float4(sigmoidf_(acc[i][0]), sigmoidf_(acc[i][1]), sigmoidf_(acc[i][2]), sigmoidf_(acc[i][3]));
            o1 = make_float4(sigmoidf_(acc[i][4]), sigmoidf_(acc[i][5]), sigmoidf_(acc[i][6]), sigmoidf_(acc[i][7]));
        } else {
            o0 = make_float4(acc[i][0], acc[i][1], acc[i][2], acc[i][3]);
            o1 = make_float4(acc[i][4], acc[i][5], acc[i][6], acc[i][7]);
        }
        *(float4*)(C + (size_t)row * N + bn + tx * 8)     = o0;
        *(float4*)(C + (size_t)row * N + bn + tx * 8 + 4) = o1;
    }
}

// ---------------- pooling (deterministic 2-pass) ----------------
__global__ __launch_bounds__(256) void pool_partial_kernel(
    const float* __restrict__ Y, float* __restrict__ Psum, float* __restrict__ Pmax)
{
    int b = blockIdx.x, t = threadIdx.x;           // 64 blocks x 256 threads
    float s0 = 0.f, s1 = 0.f, m0 = -1e30f, m1 = -1e30f;
    int base = b * 256;
    for (int r = 0; r < 256; r++) {
        const float* row = Y + (size_t)(base + r) * CDIM;
        float v0 = row[t], v1 = row[t + 256];
        s0 += v0; s1 += v1;
        m0 = fmaxf(m0, v0); m1 = fmaxf(m1, v1);
    }
    Psum[b * CDIM + t] = s0;       Psum[b * CDIM + t + 256] = s1;
    Pmax[b * CDIM + t] = m0;       Pmax[b * CDIM + t + 256] = m1;
}

__global__ __launch_bounds__(512) void pool_final_kernel(
    const float* __restrict__ Psum, const float* __restrict__ Pmax, float* __restrict__ pool)
{
    int t = threadIdx.x;   // 512
    float s = 0.f, m = -1e30f;
    for (int b = 0; b < 64; b++) {
        s += Psum[b * CDIM + t];
        m = fmaxf(m, Pmax[b * CDIM + t]);
    }
    pool[t] = s * (1.0f / (float)MROWS);
    pool[CDIM + t] = m;
}

// ---------------- channel-attention MLP ----------------
__global__ __launch_bounds__(128) void att_hidden_kernel(
    const float* __restrict__ pool, const float* __restrict__ Wa1j, float* __restrict__ hid)
{
    __shared__ float p[2 * CDIM];
    int tid = threadIdx.x;
    for (int q = tid; q < 2 * CDIM; q += 128) p[q] = pool[q];
    __syncthreads();
    int i = blockIdx.x * 128 + tid;   // 0..1023
    float sa = 0.f, sm = 0.f;
    for (int k = 0; k < CDIM; k++) {
        float w = Wa1j[(size_t)k * DDIM + i];
        sa = fmaf(p[k], w, sa);
        sm = fmaf(p[CDIM + k], w, sm);
    }
    hid[i]        = fmaxf(sa, 0.f);
    hid[DDIM + i] = fmaxf(sm, 0.f);
}

__global__ __launch_bounds__(128) void att_out_kernel(
    const float* __restrict__ hid, const float* __restrict__ Wa2j,
    float* __restrict__ att, float* __restrict__ att_out)
{
    __shared__ float hsum[DDIM];
    int tid = threadIdx.x;
    for (int q = tid; q < DDIM; q += 128) hsum[q] = hid[q] + hid[DDIM + q];
    __syncthreads();
    int c = blockIdx.x * 128 + tid;   // 0..511
    float s = 0.f;
    for (int i = 0; i < DDIM; i++)
        s = fmaf(hsum[i], Wa2j[(size_t)i * CDIM + c], s);
    float a = sigmoidf_(s);
    att[c] = a;
    att_out[c] = a;
}

// ---------------- final GEMV (O = 1) ----------------
__global__ __launch_bounds__(256) void gemv_kernel(
    const float* __restrict__ X, const float* __restrict__ Wd, float* __restrict__ y)
{
    __shared__ float w[CDIM];
    int tid = threadIdx.x;
    w[tid] = Wd[tid]; w[tid + 256] = Wd[tid + 256];
    __syncthreads();
    int warp = tid >> 5, lane = tid & 31;
    int row = blockIdx.x * 8 + warp;
    const float* x = X + (size_t)row * CDIM;
    float s = 0.f;
#pragma unroll
    for (int i = 0; i < 16; i++)
        s = fmaf(x[lane + 32 * i], w[lane + 32 * i], s);
#pragma unroll
    for (int o = 16; o; o >>= 1) s += __shfl_down_sync(0xffffffffu, s, o);
    if (lane == 0) y[row] = s;
}

// ---------------- host orchestration ----------------
static void launch_gemm(const float* A, const float* B, float* C,
                        int M, int N, int K, bool sig,
                        const float* ascale, const float* aadd)
{
    dim3 g(N / 128, M / 128), b(256);
    if (sig) {
        if (ascale) gemm_kernel<true, true, false><<<g, b>>>(A, B, C, M, N, K, ascale, nullptr);
        else        gemm_kernel<true, false, false><<<g, b>>>(A, B, C, M, N, K, nullptr, nullptr);
    } else {
        if (aadd)   gemm_kernel<false, false, true><<<g, b>>>(A, B, C, M, N, K, nullptr, aadd);
        else        gemm_kernel<false, false, false><<<g, b>>>(A, B, C, M, N, K, nullptr, nullptr);
    }
}

extern "C" void kernel_launch(void* const* d_in, const int* in_sizes, int n_in,
                              void* d_out, int out_size)
{
    const float* X   = (const float*)d_in[0];
    const float* U   = (const float*)d_in[1];
    const float* W   = (const float*)d_in[2];
    const float* V   = (const float*)d_in[3];
    const float* Wd1 = (const float*)d_in[4];
    const float* Wd2 = (const float*)d_in[5];
    const float* Wd3 = (const float*)d_in[6];
    const float* Wd  = (const float*)d_in[7];
    const float* Wa1 = (const float*)d_in[8];
    const float* Wa2 = (const float*)d_in[9];

    float* out      = (float*)d_out;
    float* out_y    = out;                       // [16384]
    float* out_att  = out + MROWS;               // [2,1,512]
    float* out_data = out_att + NBLK * CDIM;     // [2,16384,512]

    float *xu, *h, *a1, *a2, *xn, *ps, *pm, *pool, *hid, *att;
    unsigned long long* hpk;
    cudaGetSymbolAddress((void**)&xu,    g_XU);
    cudaGetSymbolAddress((void**)&h,     g_H);
    cudaGetSymbolAddress((void**)&a1,    g_A1);
    cudaGetSymbolAddress((void**)&a2,    g_A2);
    cudaGetSymbolAddress((void**)&xn,    g_Xn);
    cudaGetSymbolAddress((void**)&ps,    g_Psum);
    cudaGetSymbolAddress((void**)&pm,    g_Pmax);
    cudaGetSymbolAddress((void**)&pool,  g_pool);
    cudaGetSymbolAddress((void**)&hid,   g_hid);
    cudaGetSymbolAddress((void**)&att,   g_att);
    cudaGetSymbolAddress((void**)&hpk,   g_hpk);

    for (int j = 0; j < NBLK; j++) {
        const float* Ain  = (j == 0) ? X : xn;
        const float* Aadd = (j == 0) ? nullptr : X;

        // XU = (Ain [+ X]) @ U     (no activation)
        launch_gemm(Ain, U, xu, MROWS, CDIM, CDIM, false, nullptr, Aadd);

        // sequential RNN over M steps -> H (reset exchange state first)
        rnn_init_kernel<<<1, 1024>>>(hpk);
        rnn_kernel<<<RNN_CTAS, 512>>>(xu, W, h, MROWS, hpk);

        // Y = sigmoid(H @ V) written straight into the output "data" slab
        float* Yj = out_data + (size_t)j * MROWS * CDIM;
        launch_gemm(h, V, Yj, MROWS, CDIM, CDIM, true, nullptr, nullptr);

        // channel attention
        pool_partial_kernel<<<64, 256>>>(Yj, ps, pm);
        pool_final_kernel<<<1, 512>>>(ps, pm, pool);
        att_hidden_kernel<<<8, 128>>>(pool, Wa1 + (size_t)j * CDIM * DDIM, hid);
        att_out_kernel<<<4, 128>>>(hid, Wa2 + (size_t)j * DDIM * CDIM, att,
                                   out_att + (size_t)j * CDIM);

        // dense stack with att folded into A-loads of the first GEMM
        launch_gemm(Yj, Wd1, a1, MROWS, DDIM, CDIM, true, att, nullptr);
        launch_gemm(a1, Wd2, a2, MROWS, DDIM, DDIM, true, nullptr, nullptr);
        launch_gemm(a2, Wd3, xn, MROWS, CDIM, DDIM, true, nullptr, nullptr);
    }

    // y_hat = Xn @ Wd  (O=1)
    gemv_kernel<<<MROWS / 8, 256>>>(xn, Wd, out_y);
}

// round 11
// speedup vs baseline: 2.0671x; 1.3877x over previous
#include <cuda_runtime.h>
#include <cstdint>

#define MROWS 16384
#define CDIM  512
#define DDIM  1024
#define NBLK  2

#define RNN_CTAS 16          // CTAs in RNN kernel; each owns 512/16 = 32 columns
#define RCOLS    32          // columns per CTA == stripe width

// ---------------- scratch (static device globals; no allocation) ----------------
__device__ float g_XU[MROWS * CDIM];
__device__ float g_H [MROWS * CDIM];
__device__ float g_A1[MROWS * DDIM];
__device__ float g_A2[MROWS * DDIM];
__device__ float g_Xn[MROWS * CDIM];
__device__ float g_Psum[64 * CDIM];
__device__ float g_Pmax[64 * CDIM];
__device__ float g_pool[2 * CDIM];     // [avg | max]
__device__ float g_hid[2 * DDIM];      // [hid_avg | hid_max]
__device__ float g_att[CDIM];
__device__ unsigned long long g_hpk[2 * CDIM];   // packed {tag,value} h exchange, double-buffered

__device__ __forceinline__ float sigmoidf_(float x) {
    return __fdividef(1.0f, 1.0f + __expf(-x));
}

// Exchange ops. BOTH sides relaxed.gpu: morally strong => the aligned 64-bit
// {tag|value} word is single-copy-atomic (weak ld.cv tears it: R7/R8).
// No release on publish: GPU-scope release stalls until ALL prior ops are
// performed (fence machinery, hundreds of cycles on the serial cross-CTA
// chain every step). Correctness without it: hv's VALUE data-depends on all
// of this CTA's step-t poll loads (partial[] smem -> __syncthreads STS-drain
// -> tail LDS/FMA), so the published word cannot become visible before those
// loads performed — the only property the tag-induction WAR proof needs.
// Future-tag acceptance is impossible at pipeline depth 2. No deadlock path:
// tags are monotone, every producer's publish depends only on words already
// published, all 16 CTAs are co-resident (grid 16 << 148 SMs).
__device__ __forceinline__ unsigned long long ld_rlx64_(const unsigned long long* p) {
    unsigned long long v;
    asm volatile("ld.relaxed.gpu.global.b64 %0, [%1];" : "=l"(v) : "l"(p) : "memory");
    return v;
}
__device__ __forceinline__ void st_rlx64_(unsigned long long* p, unsigned long long v) {
    asm volatile("st.relaxed.gpu.global.b64 [%0], %1;" :: "l"(p), "l"(v) : "memory");
}

// ---------------- RNN state reset (before each RNN launch; graph-replay safe) ----
__global__ void rnn_init_kernel(unsigned long long* hpk)
{
    hpk[threadIdx.x] = 0ULL;             // 1024 threads: value = 0.0f, tag = 0
}

// =================================================================================
// Sequential RNN, stripe-pipelined across 16 CTAs (no clusters).
//   - CTA r owns output columns [r*32, r*32+32); publishes packed {tag|value}
//     words, parity-double-buffered by t&1.
//   - Warp w polls ONLY the 32 words of CTA w (its k-stripe), stages, and
//     immediately runs that stripe's 32 FMAs — waits on late producers overlap
//     with compute on stripes already arrived.
//   - XU ring: warp 1 keeps a 4-slot smem ring (store t+2's value, issue t+3's
//     load each iter), keeping the XU DRAM load off the serial path.
//   - Tail (warp 0): reduce 16 partials, sigmoid, publish FIRST, then store H
//     (H vs next GEMM is ordered by the kernel boundary).
// WAR safety by tag induction: tag t+1 from CTA c implies c's step-t tail ran,
// after c's __syncthreads, hence after all c's warps' step-t loads completed.
// =================================================================================
__global__ void __launch_bounds__(512)
rnn_kernel(const float* __restrict__ XU, const float* __restrict__ W,
           float* __restrict__ H, int M, unsigned long long* hpk)
{
    __shared__ __align__(16) float hs[16][RCOLS];        // staged h, stripe-major
    __shared__ float partial[2][16][RCOLS + 1];          // padded (bank spread)
    __shared__ float xubuf[4][RCOLS];                    // XU ring: slot s%4 = step s

    int rank = blockIdx.x;
    int tid = threadIdx.x;
    int w = tid >> 5, l = tid & 31;
    int col = (rank << 5) + l;           // this CTA's output column

    // W stripe: thread (w,l) holds W[w*32+i][rank*32+l]
    float Wreg[RCOLS];
#pragma unroll
    for (int i = 0; i < RCOLS; i++)
        Wreg[i] = W[(size_t)((w << 5) + i) * CDIM + (rank << 5) + l];

    // XU ring preload (warp 1): slots 0,1 = steps 0,1; register = step 2
    float xu_reg = 0.0f;
    if (w == 1) {
        xubuf[0][l] = XU[col];
        xubuf[1][l] = XU[(size_t)1 * CDIM + col];
        xu_reg      = XU[(size_t)2 * CDIM + col];
    }

    // loop-invariant pointers
    const unsigned long long* poll_par0 = hpk + (w << 5) + l;         // read when t odd
    const unsigned long long* poll_par1 = poll_par0 + 512;            // read when t even
    unsigned long long* pub_par0 = hpk + col;                         // written when t even
    unsigned long long* pub_par1 = pub_par0 + 512;                    // written when t odd

    for (int t = 0; t < M; t++) {
        int cur = t & 1;

        // ---- poll + stage this warp's stripe (one packed word per thread) ----
        const unsigned long long* src = cur ? poll_par0 : poll_par1;
        unsigned long long pk = ld_rlx64_(src);
        while ((int)(pk >> 32) < t) pk = ld_rlx64_(src);
        hs[w][l] = __uint_as_float((unsigned)(pk & 0xffffffffu));
        __syncwarp();

        // ---- stripe FMA: 32 MACs per thread, broadcast LDS of staged h ----
        float a0 = 0.f, a1 = 0.f, a2 = 0.f, a3 = 0.f;
        const float4* h4 = reinterpret_cast<const float4*>(hs[w]);
#pragma unroll
        for (int i = 0; i < 8; i++) {
            float4 h = h4[i];
            a0 = fmaf(h.x, Wreg[4 * i + 0], a0);
            a1 = fmaf(h.y, Wreg[4 * i + 1], a1);
            a2 = fmaf(h.z, Wreg[4 * i + 2], a2);
            a3 = fmaf(h.w, Wreg[4 * i + 3], a3);
        }
        partial[cur][w][l] = (a0 + a1) + (a2 + a3);

        // ---- warp 1: service the XU ring (value arrived ~1 iter ago; no stall) ----
        if (w == 1) {
            if (t + 2 < M) xubuf[(t + 2) & 3][l] = xu_reg;
            xu_reg = (t + 3 < M) ? XU[(size_t)(t + 3) * CDIM + col] : 0.0f;
        }
        __syncthreads();

        // ---- tail: reduce 16 stripes, activate, publish FIRST, then H ----
        if (w == 0) {
            float s = xubuf[t & 3][l];
#pragma unroll
            for (int q = 0; q < 16; q++) s += partial[cur][q][l];
            float hv = sigmoidf_(s);
            unsigned long long outw =
                ((unsigned long long)(unsigned)(t + 1) << 32) |
                (unsigned long long)__float_as_uint(hv);
            st_rlx64_(cur ? pub_par1 : pub_par0, outw);
            H[(size_t)t * CDIM + col] = hv;
        }
    }
}

// =================================================================================
// fp32 SGEMM: C[M,N] (= sigmoid?)( (A (+Aadd) * ascale_k) @ B )
// 128x128 tile, BK=16, 256 threads, 8x8 per thread, register-staged double buffer.
// =================================================================================
template<bool SCALE, bool ADD>
__device__ __forceinline__ void gemm_load_tiles(
    const float* Ap0, const float* Ap1, const float* Ad0, const float* Ad1,
    const float* Bp0, const float* Bp1, const float* __restrict__ ascale,
    int k0, int ac4, int N,
    float4& a0, float4& a1, float4& b0, float4& b1)
{
    a0 = *(const float4*)(Ap0 + k0);
    a1 = *(const float4*)(Ap1 + k0);
    if (ADD) {
        float4 d0 = *(const float4*)(Ad0 + k0);
        float4 d1 = *(const float4*)(Ad1 + k0);
        a0.x += d0.x; a0.y += d0.y; a0.z += d0.z; a0.w += d0.w;
        a1.x += d1.x; a1.y += d1.y; a1.z += d1.z; a1.w += d1.w;
    }
    if (SCALE) {
        float4 s = *(const float4*)(ascale + k0 + ac4);
        a0.x *= s.x; a0.y *= s.y; a0.z *= s.z; a0.w *= s.w;
        a1.x *= s.x; a1.y *= s.y; a1.z *= s.z; a1.w *= s.w;
    }
    b0 = *(const float4*)(Bp0 + (size_t)k0 * N);
    b1 = *(const float4*)(Bp1 + (size_t)k0 * N);
}

template<bool SIG, bool SCALE, bool ADD>
__global__ __launch_bounds__(256) void gemm_kernel(
    const float* __restrict__ A, const float* __restrict__ B, float* __restrict__ C,
    int M, int N, int K,
    const float* __restrict__ ascale, const float* __restrict__ aadd)
{
    __shared__ __align__(16) float As[16][132];
    __shared__ __align__(16) float Bs[16][132];

    int tid = threadIdx.x;
    int bm = blockIdx.y * 128, bn = blockIdx.x * 128;

    int ar  = tid >> 2;          // 0..63
    int ac4 = (tid & 3) << 2;    // 0,4,8,12
    int br  = tid >> 5;          // 0..7
    int bc4 = (tid & 31) << 2;   // 0..124

    const float* Ap0 = A + (size_t)(bm + ar) * K + ac4;
    const float* Ap1 = A + (size_t)(bm + ar + 64) * K + ac4;
    const float* Ad0 = ADD ? (aadd + (size_t)(bm + ar) * K + ac4) : nullptr;
    const float* Ad1 = ADD ? (aadd + (size_t)(bm + ar + 64) * K + ac4) : nullptr;
    const float* Bp0 = B + (size_t)br * N + bn + bc4;
    const float* Bp1 = B + (size_t)(br + 8) * N + bn + bc4;

    float4 a0, a1, b0, b1;
    float acc[8][8];
#pragma unroll
    for (int i = 0; i < 8; i++)
#pragma unroll
        for (int j = 0; j < 8; j++) acc[i][j] = 0.0f;

    gemm_load_tiles<SCALE, ADD>(Ap0, Ap1, Ad0, Ad1, Bp0, Bp1, ascale, 0, ac4, N, a0, a1, b0, b1);
    // store tile 0
    As[ac4 + 0][ar] = a0.x; As[ac4 + 1][ar] = a0.y; As[ac4 + 2][ar] = a0.z; As[ac4 + 3][ar] = a0.w;
    As[ac4 + 0][ar + 64] = a1.x; As[ac4 + 1][ar + 64] = a1.y; As[ac4 + 2][ar + 64] = a1.z; As[ac4 + 3][ar + 64] = a1.w;
    *(float4*)&Bs[br][bc4] = b0;
    *(float4*)&Bs[br + 8][bc4] = b1;
    __syncthreads();

    int ty = tid >> 4, tx = tid & 15;
    int ntiles = K >> 4;

    for (int kt = 1; kt <= ntiles; kt++) {
        if (kt < ntiles)
            gemm_load_tiles<SCALE, ADD>(Ap0, Ap1, Ad0, Ad1, Bp0, Bp1, ascale, kt * 16, ac4, N, a0, a1, b0, b1);
#pragma unroll
        for (int kk = 0; kk < 16; kk++) {
            float4 af0 = *(const float4*)&As[kk][ty * 8];
            float4 af1 = *(const float4*)&As[kk][ty * 8 + 4];
            float4 bf0 = *(const float4*)&Bs[kk][tx * 8];
            float4 bf1 = *(const float4*)&Bs[kk][tx * 8 + 4];
            float av[8] = {af0.x, af0.y, af0.z, af0.w, af1.x, af1.y, af1.z, af1.w};
            float bv[8] = {bf0.x, bf0.y, bf0.z, bf0.w, bf1.x, bf1.y, bf1.z, bf1.w};
#pragma unroll
            for (int i = 0; i < 8; i++)
#pragma unroll
                for (int j = 0; j < 8; j++)
                    acc[i][j] = fmaf(av[i], bv[j], acc[i][j]);
        }
        __syncthreads();
        if (kt < ntiles) {
            As[ac4 + 0][ar] = a0.x; As[ac4 + 1][ar] = a0.y; As[ac4 + 2][ar] = a0.z; As[ac4 + 3][ar] = a0.w;
            As[ac4 + 0][ar + 64] = a1.x; As[ac4 + 1][ar + 64] = a1.y; As[ac4 + 2][ar + 64] = a1.z; As[ac4 + 3][ar + 64] = a1.w;
            *(float4*)&Bs[br][bc4] = b0;
            *(float4*)&Bs[br + 8][bc4] = b1;
            __syncthreads();
        }
    }

#pragma unroll
    for (int i = 0; i < 8; i++) {
        int row = bm + ty * 8 + i;
        float4 o0, o1;
        if (SIG) {
            o0 = make_float4(sigmoidf_(acc[i][0]), sigmoidf_(acc[i][1]), sigmoidf_(acc[i][2]), sigmoidf_(acc[i][3]));
            o1 = make_float4(sigmoidf_(acc[i][4]), sigmoidf_(acc[i][5]), sigmoidf_(acc[i][6]), sigmoidf_(acc[i][7]));
        } else {
            o0 = make_float4(acc[i][0], acc[i][1], acc[i][2], acc[i][3]);
            o1 = make_float4(acc[i][4], acc[i][5], acc[i][6], acc[i][7]);
        }
        *(float4*)(C + (size_t)row * N + bn + tx * 8)     = o0;
        *(float4*)(C + (size_t)row * N + bn + tx * 8 + 4) = o1;
    }
}

// ---------------- pooling (deterministic 2-pass) ----------------
__global__ __launch_bounds__(256) void pool_partial_kernel(
    const float* __restrict__ Y, float* __restrict__ Psum, float* __restrict__ Pmax)
{
    int b = blockIdx.x, t = threadIdx.x;           // 64 blocks x 256 threads
    float s0 = 0.f, s1 = 0.f, m0 = -1e30f, m1 = -1e30f;
    int base = b * 256;
    for (int r = 0; r < 256; r++) {
        const float* row = Y + (size_t)(base + r) * CDIM;
        float v0 = row[t], v1 = row[t + 256];
        s0 += v0; s1 += v1;
        m0 = fmaxf(m0, v0); m1 = fmaxf(m1, v1);
    }
    Psum[b * CDIM + t] = s0;       Psum[b * CDIM + t + 256] = s1;
    Pmax[b * CDIM + t] = m0;       Pmax[b * CDIM + t + 256] = m1;
}

__global__ __launch_bounds__(512) void pool_final_kernel(
    const float* __restrict__ Psum, const float* __restrict__ Pmax, float* __restrict__ pool)
{
    int t = threadIdx.x;   // 512
    float s = 0.f, m = -1e30f;
    for (int b = 0; b < 64; b++) {
        s += Psum[b * CDIM + t];
        m = fmaxf(m, Pmax[b * CDIM + t]);
    }
    pool[t] = s * (1.0f / (float)MROWS);
    pool[CDIM + t] = m;
}

// ---------------- channel-attention MLP ----------------
__global__ __launch_bounds__(128) void att_hidden_kernel(
    const float* __restrict__ pool, const float* __restrict__ Wa1j, float* __restrict__ hid)
{
    __shared__ float p[2 * CDIM];
    int tid = threadIdx.x;
    for (int q = tid; q < 2 * CDIM; q += 128) p[q] = pool[q];
    __syncthreads();
    int i = blockIdx.x * 128 + tid;   // 0..1023
    float sa = 0.f, sm = 0.f;
    for (int k = 0; k < CDIM; k++) {
        float w = Wa1j[(size_t)k * DDIM + i];
        sa = fmaf(p[k], w, sa);
        sm = fmaf(p[CDIM + k], w, sm);
    }
    hid[i]        = fmaxf(sa, 0.f);
    hid[DDIM + i] = fmaxf(sm, 0.f);
}

__global__ __launch_bounds__(128) void att_out_kernel(
    const float* __restrict__ hid, const float* __restrict__ Wa2j,
    float* __restrict__ att, float* __restrict__ att_out)
{
    __shared__ float hsum[DDIM];
    int tid = threadIdx.x;
    for (int q = tid; q < DDIM; q += 128) hsum[q] = hid[q] + hid[DDIM + q];
    __syncthreads();
    int c = blockIdx.x * 128 + tid;   // 0..511
    float s = 0.f;
    for (int i = 0; i < DDIM; i++)
        s = fmaf(hsum[i], Wa2j[(size_t)i * CDIM + c], s);
    float a = sigmoidf_(s);
    att[c] = a;
    att_out[c] = a;
}

// ---------------- final GEMV (O = 1) ----------------
__global__ __launch_bounds__(256) void gemv_kernel(
    const float* __restrict__ X, const float* __restrict__ Wd, float* __restrict__ y)
{
    __shared__ float w[CDIM];
    int tid = threadIdx.x;
    w[tid] = Wd[tid]; w[tid + 256] = Wd[tid + 256];
    __syncthreads();
    int warp = tid >> 5, lane = tid & 31;
    int row = blockIdx.x * 8 + warp;
    const float* x = X + (size_t)row * CDIM;
    float s = 0.f;
#pragma unroll
    for (int i = 0; i < 16; i++)
        s = fmaf(x[lane + 32 * i], w[lane + 32 * i], s);
#pragma unroll
    for (int o = 16; o; o >>= 1) s += __shfl_down_sync(0xffffffffu, s, o);
    if (lane == 0) y[row] = s;
}

// ---------------- host orchestration ----------------
static void launch_gemm(const float* A, const float* B, float* C,
                        int M, int N, int K, bool sig,
                        const float* ascale, const float* aadd)
{
    dim3 g(N / 128, M / 128), b(256);
    if (sig) {
        if (ascale) gemm_kernel<true, true, false><<<g, b>>>(A, B, C, M, N, K, ascale, nullptr);
        else        gemm_kernel<true, false, false><<<g, b>>>(A, B, C, M, N, K, nullptr, nullptr);
    } else {
        if (aadd)   gemm_kernel<false, false, true><<<g, b>>>(A, B, C, M, N, K, nullptr, aadd);
        else        gemm_kernel<false, false, false><<<g, b>>>(A, B, C, M, N, K, nullptr, nullptr);
    }
}

extern "C" void kernel_launch(void* const* d_in, const int* in_sizes, int n_in,
                              void* d_out, int out_size)
{
    const float* X   = (const float*)d_in[0];
    const float* U   = (const float*)d_in[1];
    const float* W   = (const float*)d_in[2];
    const float* V   = (const float*)d_in[3];
    const float* Wd1 = (const float*)d_in[4];
    const float* Wd2 = (const float*)d_in[5];
    const float* Wd3 = (const float*)d_in[6];
    const float* Wd  = (const float*)d_in[7];
    const float* Wa1 = (const float*)d_in[8];
    const float* Wa2 = (const float*)d_in[9];

    float* out      = (float*)d_out;
    float* out_y    = out;                       // [16384]
    float* out_att  = out + MROWS;               // [2,1,512]
    float* out_data = out_att + NBLK * CDIM;     // [2,16384,512]

    float *xu, *h, *a1, *a2, *xn, *ps, *pm, *pool, *hid, *att;
    unsigned long long* hpk;
    cudaGetSymbolAddress((void**)&xu,    g_XU);
    cudaGetSymbolAddress((void**)&h,     g_H);
    cudaGetSymbolAddress((void**)&a1,    g_A1);
    cudaGetSymbolAddress((void**)&a2,    g_A2);
    cudaGetSymbolAddress((void**)&xn,    g_Xn);
    cudaGetSymbolAddress((void**)&ps,    g_Psum);
    cudaGetSymbolAddress((void**)&pm,    g_Pmax);
    cudaGetSymbolAddress((void**)&pool,  g_pool);
    cudaGetSymbolAddress((void**)&hid,   g_hid);
    cudaGetSymbolAddress((void**)&att,   g_att);
    cudaGetSymbolAddress((void**)&hpk,   g_hpk);

    for (int j = 0; j < NBLK; j++) {
        const float* Ain  = (j == 0) ? X : xn;
        const float* Aadd = (j == 0) ? nullptr : X;

        // XU = (Ain [+ X]) @ U     (no activation)
        launch_gemm(Ain, U, xu, MROWS, CDIM, CDIM, false, nullptr, Aadd);

        // sequential RNN over M steps -> H (reset exchange state first)
        rnn_init_kernel<<<1, 1024>>>(hpk);
        rnn_kernel<<<RNN_CTAS, 512>>>(xu, W, h, MROWS, hpk);

        // Y = sigmoid(H @ V) written straight into the output "data" slab
        float* Yj = out_data + (size_t)j * MROWS * CDIM;
        launch_gemm(h, V, Yj, MROWS, CDIM, CDIM, true, nullptr, nullptr);

        // channel attention
        pool_partial_kernel<<<64, 256>>>(Yj, ps, pm);
        pool_final_kernel<<<1, 512>>>(ps, pm, pool);
        att_hidden_kernel<<<8, 128>>>(pool, Wa1 + (size_t)j * CDIM * DDIM, hid);
        att_out_kernel<<<4, 128>>>(hid, Wa2 + (size_t)j * DDIM * CDIM, att,
                                   out_att + (size_t)j * CDIM);

        // dense stack with att folded into A-loads of the first GEMM
        launch_gemm(Yj, Wd1, a1, MROWS, DDIM, CDIM, true, att, nullptr);
        launch_gemm(a1, Wd2, a2, MROWS, DDIM, DDIM, true, nullptr, nullptr);
        launch_gemm(a2, Wd3, xn, MROWS, CDIM, DDIM, true, nullptr, nullptr);
    }

    // y_hat = Xn @ Wd  (O=1)
    gemv_kernel<<<MROWS / 8, 256>>>(xn, Wd, out_y);
}